// round 3
// baseline (speedup 1.0000x reference)
#include <cuda_runtime.h>
#include <cstdint>

// Problem constants (fixed by the dataset)
#define N_NODES 50000
#define N_EDGES 800000
#define F_IN   128
#define F_H1   256   // layer1 output
#define F_H    128   // layer2 output
#define F_OUT  32

// ---------------- scratch (static device globals — no allocation) ----------
__device__ int   g_count [N_NODES];
__device__ float g_dinv  [N_NODES];
__device__ int   g_rowptr[N_NODES + 1];
__device__ int   g_cursor[N_NODES];
__device__ int   g_col   [N_EDGES];

__device__ float g_aggx[(size_t)N_NODES * F_IN];   // agg(x)
__device__ float g_h1  [(size_t)N_NODES * F_H1];   // relu(agg(x)@W1+b1)
__device__ float g_g2  [(size_t)N_NODES * F_H];    // h1@W2
__device__ float g_h2  [(size_t)N_NODES * F_H];    // relu(agg(g2)+b2)
__device__ float g_g3  [(size_t)N_NODES * F_OUT];  // h2@W3

// ---------------- graph preprocessing --------------------------------------
__global__ void zero_counts_kernel(int n) {
    int i = blockIdx.x * blockDim.x + threadIdx.x;
    if (i < n) g_count[i] = 0;
}

// edge_index is int32 (JAX x64 disabled): layout [2, E] row-major,
// src = ei[0:E], dst = ei[E:2E].
__global__ void degree_kernel(const int* __restrict__ ei, int e) {
    int i = blockIdx.x * blockDim.x + threadIdx.x;
    if (i < e) {
        int dst = ei[e + i];
        atomicAdd(&g_count[dst], 1);
    }
}

__global__ void dinv_kernel(int n) {
    int i = blockIdx.x * blockDim.x + threadIdx.x;
    if (i < n) g_dinv[i] = rsqrtf((float)(g_count[i] + 1));  // +1 self-loop
}

// Single-block exclusive scan of g_count -> g_rowptr (and g_cursor copy).
__global__ void scan_kernel(int n) {
    __shared__ int temp[1024];
    __shared__ int carry;
    if (threadIdx.x == 0) carry = 0;
    __syncthreads();
    for (int base = 0; base < n; base += 1024) {
        int i = base + threadIdx.x;
        int v = (i < n) ? g_count[i] : 0;
        temp[threadIdx.x] = v;
        __syncthreads();
        #pragma unroll
        for (int off = 1; off < 1024; off <<= 1) {
            int t = (threadIdx.x >= off) ? temp[threadIdx.x - off] : 0;
            __syncthreads();
            temp[threadIdx.x] += t;
            __syncthreads();
        }
        int incl = temp[threadIdx.x];
        if (i < n) {
            int excl = carry + incl - v;
            g_rowptr[i] = excl;
            g_cursor[i] = excl;
        }
        __syncthreads();
        if (threadIdx.x == 1023) carry += temp[1023];
        __syncthreads();
    }
    if (threadIdx.x == 0) g_rowptr[n] = carry;
}

__global__ void fill_csr_kernel(const int* __restrict__ ei, int e) {
    int i = blockIdx.x * blockDim.x + threadIdx.x;
    if (i < e) {
        int src = ei[i];
        int dst = ei[e + i];
        int pos = atomicAdd(&g_cursor[dst], 1);
        g_col[pos] = src;
    }
}

// ---------------- pull-based aggregation ------------------------------------
// out[dst] = dinv[dst] * ( sum_{src in N(dst)} dinv[src]*g[src] + dinv[dst]*g[dst] )
// blockDim = (F, nodes_per_block)
template <int F, bool BIAS, bool RELU>
__global__ void agg_kernel(const float* __restrict__ g,
                           const float* __restrict__ bias,
                           float* __restrict__ out, int n) {
    int node = blockIdx.x * blockDim.y + threadIdx.y;
    if (node >= n) return;
    int f = threadIdx.x;
    float di = g_dinv[node];
    float acc = di * g[(size_t)node * F + f];   // self loop
    int e0 = g_rowptr[node];
    int e1 = g_rowptr[node + 1];
    for (int e = e0; e < e1; e++) {
        int s = g_col[e];
        acc += g_dinv[s] * __ldg(&g[(size_t)s * F + f]);
    }
    acc *= di;
    if (BIAS) acc += bias[f];
    if (RELU) acc = fmaxf(acc, 0.0f);
    out[(size_t)node * F + f] = acc;
}

// ---------------- SMEM-tiled fp32 GEMM with register blocking --------------
// C[M,N] = A[M,K] @ B[K,N] (+bias)(+relu), all row-major.
template <int BM, int BN, int BK, int TM, int TN, bool BIAS, bool RELU>
__global__ void gemm_kernel(const float* __restrict__ A,
                            const float* __restrict__ B,
                            const float* __restrict__ bias,
                            float* __restrict__ C,
                            int M, int K, int N) {
    constexpr int NT = (BM / TM) * (BN / TN);   // threads per block
    constexpr int TC = BN / TN;
    __shared__ float As[BK][BM];   // A tile transposed for coalesced micro-loads
    __shared__ float Bs[BK][BN];

    int tid  = threadIdx.x;
    int brow = blockIdx.y * BM;
    int bcol = blockIdx.x * BN;
    int trow = (tid / TC) * TM;
    int tcol = (tid % TC) * TN;

    float acc[TM][TN];
    #pragma unroll
    for (int i = 0; i < TM; i++)
        #pragma unroll
        for (int j = 0; j < TN; j++) acc[i][j] = 0.0f;

    for (int k0 = 0; k0 < K; k0 += BK) {
        #pragma unroll
        for (int i = tid; i < BM * BK; i += NT) {
            int r = i / BK, c = i % BK;
            int gr = brow + r;
            As[c][r] = (gr < M) ? A[(size_t)gr * K + k0 + c] : 0.0f;
        }
        #pragma unroll
        for (int i = tid; i < BK * BN; i += NT) {
            int r = i / BN, c = i % BN;
            Bs[r][c] = B[(size_t)(k0 + r) * N + bcol + c];
        }
        __syncthreads();
        #pragma unroll
        for (int k = 0; k < BK; k++) {
            float a[TM], b[TN];
            #pragma unroll
            for (int i = 0; i < TM; i++) a[i] = As[k][trow + i];
            #pragma unroll
            for (int j = 0; j < TN; j++) b[j] = Bs[k][tcol + j];
            #pragma unroll
            for (int i = 0; i < TM; i++)
                #pragma unroll
                for (int j = 0; j < TN; j++)
                    acc[i][j] += a[i] * b[j];
        }
        __syncthreads();
    }

    #pragma unroll
    for (int i = 0; i < TM; i++) {
        int gr = brow + trow + i;
        if (gr >= M) continue;
        #pragma unroll
        for (int j = 0; j < TN; j++) {
            float v = acc[i][j];
            if (BIAS) v += bias[bcol + tcol + j];
            if (RELU) v = fmaxf(v, 0.0f);
            C[(size_t)gr * N + bcol + tcol + j] = v;
        }
    }
}

// ---------------- driver -----------------------------------------------------
extern "C" void kernel_launch(void* const* d_in, const int* in_sizes, int n_in,
                              void* d_out, int out_size) {
    const float* x  = (const float*)d_in[0];
    const int*   ei = (const int*)d_in[1];       // int32! (JAX x64 disabled)
    const float* W1 = (const float*)d_in[2];
    const float* b1 = (const float*)d_in[3];
    const float* W2 = (const float*)d_in[4];
    const float* b2 = (const float*)d_in[5];
    const float* W3 = (const float*)d_in[6];
    const float* b3 = (const float*)d_in[7];
    float*       out = (float*)d_out;

    const int n = in_sizes[0] / F_IN;     // 50000
    const int e = in_sizes[1] / 2;        // 800000

    // Resolve REAL device addresses of the __device__ scratch globals.
    float *p_aggx, *p_h1, *p_g2, *p_h2, *p_g3;
    cudaGetSymbolAddress((void**)&p_aggx, g_aggx);
    cudaGetSymbolAddress((void**)&p_h1,   g_h1);
    cudaGetSymbolAddress((void**)&p_g2,   g_g2);
    cudaGetSymbolAddress((void**)&p_h2,   g_h2);
    cudaGetSymbolAddress((void**)&p_g3,   g_g3);

    // --- graph preprocessing: degree, dinv, CSR-by-dst ---
    zero_counts_kernel<<<(n + 255) / 256, 256>>>(n);
    degree_kernel<<<(e + 255) / 256, 256>>>(ei, e);
    dinv_kernel<<<(n + 255) / 256, 256>>>(n);
    scan_kernel<<<1, 1024>>>(n);
    fill_csr_kernel<<<(e + 255) / 256, 256>>>(ei, e);

    // --- Layer 1: agg(x) then GEMM(128->256) + b1 + relu ---
    {
        dim3 blk(F_IN, 2);
        agg_kernel<F_IN, false, false><<<(n + 1) / 2, blk>>>(x, nullptr, p_aggx, n);
    }
    {
        dim3 grid(F_H1 / 128, (n + 127) / 128);
        gemm_kernel<128, 128, 16, 8, 8, true, true><<<grid, 256>>>(
            p_aggx, W1, b1, p_h1, n, F_IN, F_H1);
    }

    // --- Layer 2: GEMM(256->128) then agg + b2 + relu ---
    {
        dim3 grid(F_H / 128, (n + 127) / 128);
        gemm_kernel<128, 128, 16, 8, 8, false, false><<<grid, 256>>>(
            p_h1, W2, nullptr, p_g2, n, F_H1, F_H);
    }
    {
        dim3 blk(F_H, 2);
        agg_kernel<F_H, true, true><<<(n + 1) / 2, blk>>>(p_g2, b2, p_h2, n);
    }

    // --- Layer 3: GEMM(128->32) then agg + b3 ---
    {
        dim3 grid(F_OUT / 32, (n + 127) / 128);
        gemm_kernel<128, 32, 16, 8, 2, false, false><<<grid, 256>>>(
            p_h2, W3, nullptr, p_g3, n, F_H, F_OUT);
    }
    {
        dim3 blk(F_OUT, 8);
        agg_kernel<F_OUT, true, false><<<(n + 7) / 8, blk>>>(p_g3, b3, out, n);
    }
}

// round 4
// speedup vs baseline: 1.5733x; 1.5733x over previous
#include <cuda_runtime.h>
#include <cstdint>

// Problem constants (fixed by the dataset)
#define N_NODES 50000
#define N_EDGES 800000
#define F_IN   128
#define F_H1   256   // layer1 output
#define F_H    128   // layer2 output
#define F_OUT  32

// ---------------- scratch (static device globals — no allocation) ----------
__device__ int   g_count [N_NODES];
__device__ float g_dinv  [N_NODES];
__device__ int   g_rowptr[N_NODES + 1];
__device__ int   g_cursor[N_NODES];
__device__ int   g_col   [N_EDGES];
__device__ int   g_bsum  [64];

__device__ float g_aggx[(size_t)N_NODES * F_IN];   // agg(x)
__device__ float g_h1  [(size_t)N_NODES * F_H1];   // relu(agg(x)@W1+b1)
__device__ float g_g2  [(size_t)N_NODES * F_H];    // h1@W2
__device__ float g_h2  [(size_t)N_NODES * F_H];    // relu(agg(g2)+b2)
__device__ float g_g3  [(size_t)N_NODES * F_OUT];  // h2@W3

// ---------------- graph preprocessing --------------------------------------
// edge_index is int32 (JAX x64 disabled): [2, E] row-major; src=ei[0:E], dst=ei[E:2E].
__global__ void degree_kernel(const int* __restrict__ ei, int e) {
    int i = blockIdx.x * blockDim.x + threadIdx.x;
    if (i < e) atomicAdd(&g_count[ei[e + i]], 1);
}

__global__ void dinv_kernel(int n) {
    int i = blockIdx.x * blockDim.x + threadIdx.x;
    if (i < n) g_dinv[i] = rsqrtf((float)(g_count[i] + 1));  // +1 self-loop
}

// --- 3-phase parallel exclusive scan of g_count -> g_rowptr ---
// Phase 1: per-block (1024-wide) scan; write local-exclusive to rowptr, block sum to g_bsum.
__global__ void scan_partial_kernel(int n) {
    __shared__ int temp[1024];
    int i = blockIdx.x * 1024 + threadIdx.x;
    int v = (i < n) ? g_count[i] : 0;
    temp[threadIdx.x] = v;
    __syncthreads();
    #pragma unroll
    for (int off = 1; off < 1024; off <<= 1) {
        int t = (threadIdx.x >= off) ? temp[threadIdx.x - off] : 0;
        __syncthreads();
        temp[threadIdx.x] += t;
        __syncthreads();
    }
    if (i < n) g_rowptr[i] = temp[threadIdx.x] - v;  // local exclusive
    if (threadIdx.x == 1023) g_bsum[blockIdx.x] = temp[1023];
}

// Phase 2: single block scans up to 64 block sums -> exclusive; writes total to rowptr[n].
__global__ void scan_bsum_kernel(int nb, int n) {
    __shared__ int t[64];
    int v = (threadIdx.x < nb) ? g_bsum[threadIdx.x] : 0;
    t[threadIdx.x] = v;
    __syncthreads();
    #pragma unroll
    for (int off = 1; off < 64; off <<= 1) {
        int u = (threadIdx.x >= off) ? t[threadIdx.x - off] : 0;
        __syncthreads();
        t[threadIdx.x] += u;
        __syncthreads();
    }
    if (threadIdx.x < nb) g_bsum[threadIdx.x] = t[threadIdx.x] - v;  // exclusive
    if (threadIdx.x == 63) g_rowptr[n] = t[63];
}

// Phase 3: add block offsets; mirror into cursor.
__global__ void scan_add_kernel(int n) {
    int i = blockIdx.x * 1024 + threadIdx.x;
    if (i < n) {
        int v = g_rowptr[i] + g_bsum[blockIdx.x];
        g_rowptr[i] = v;
        g_cursor[i] = v;
    }
}

__global__ void fill_csr_kernel(const int* __restrict__ ei, int e) {
    int i = blockIdx.x * blockDim.x + threadIdx.x;
    if (i < e) {
        int src = ei[i];
        int dst = ei[e + i];
        int pos = atomicAdd(&g_cursor[dst], 1);
        g_col[pos] = src;
    }
}

// ---------------- pull-based aggregation (float4, edge-unrolled x4) ---------
// out[dst] = dinv[dst] * ( sum_{src in N(dst)} dinv[src]*g[src] + dinv[dst]*g[dst] )
template <int F, bool BIAS, bool RELU>
__global__ void agg_kernel(const float* __restrict__ g,
                           const float* __restrict__ bias,
                           float* __restrict__ out, int n) {
    constexpr int TPN = F / 4;                  // threads per node
    int npb  = blockDim.x / TPN;                // nodes per block
    int node = blockIdx.x * npb + threadIdx.x / TPN;
    if (node >= n) return;
    int lane = threadIdx.x % TPN;

    const float4* gv = (const float4*)g;
    float di = g_dinv[node];
    float4 s = gv[(size_t)node * TPN + lane];
    float4 acc = make_float4(di * s.x, di * s.y, di * s.z, di * s.w);

    int e  = g_rowptr[node];
    int e1 = g_rowptr[node + 1];
    for (; e + 4 <= e1; e += 4) {
        int s0 = g_col[e], s1 = g_col[e + 1], s2 = g_col[e + 2], s3 = g_col[e + 3];
        float d0 = g_dinv[s0], d1 = g_dinv[s1], d2 = g_dinv[s2], d3 = g_dinv[s3];
        float4 v0 = gv[(size_t)s0 * TPN + lane];
        float4 v1 = gv[(size_t)s1 * TPN + lane];
        float4 v2 = gv[(size_t)s2 * TPN + lane];
        float4 v3 = gv[(size_t)s3 * TPN + lane];
        acc.x += d0 * v0.x + d1 * v1.x + d2 * v2.x + d3 * v3.x;
        acc.y += d0 * v0.y + d1 * v1.y + d2 * v2.y + d3 * v3.y;
        acc.z += d0 * v0.z + d1 * v1.z + d2 * v2.z + d3 * v3.z;
        acc.w += d0 * v0.w + d1 * v1.w + d2 * v2.w + d3 * v3.w;
    }
    for (; e < e1; e++) {
        int sv = g_col[e];
        float d = g_dinv[sv];
        float4 v = gv[(size_t)sv * TPN + lane];
        acc.x += d * v.x; acc.y += d * v.y; acc.z += d * v.z; acc.w += d * v.w;
    }
    acc.x *= di; acc.y *= di; acc.z *= di; acc.w *= di;
    if (BIAS) {
        float4 b = ((const float4*)bias)[lane];
        acc.x += b.x; acc.y += b.y; acc.z += b.z; acc.w += b.w;
    }
    if (RELU) {
        acc.x = fmaxf(acc.x, 0.0f); acc.y = fmaxf(acc.y, 0.0f);
        acc.z = fmaxf(acc.z, 0.0f); acc.w = fmaxf(acc.w, 0.0f);
    }
    ((float4*)out)[(size_t)node * TPN + lane] = acc;
}

// ---------------- SMEM-tiled fp32 GEMM, compile-time K, padded A tile -------
// C[M,N] = A[M,K] @ B[K,N] (+bias)(+relu), row-major.
template <int BM, int BN, int BK, int TM, int TN, int K, bool BIAS, bool RELU>
__global__ void gemm_kernel(const float* __restrict__ A,
                            const float* __restrict__ B,
                            const float* __restrict__ bias,
                            float* __restrict__ C,
                            int M, int N) {
    constexpr int NT = (BM / TM) * (BN / TN);   // threads per block
    constexpr int TC = BN / TN;
    __shared__ float As[BK][BM + 4];   // A transposed; +4 pad kills STS conflicts
    __shared__ float Bs[BK][BN];

    int tid  = threadIdx.x;
    int brow = blockIdx.y * BM;
    int bcol = blockIdx.x * BN;
    int trow = (tid / TC) * TM;
    int tcol = (tid % TC) * TN;

    float acc[TM][TN];
    #pragma unroll
    for (int i = 0; i < TM; i++)
        #pragma unroll
        for (int j = 0; j < TN; j++) acc[i][j] = 0.0f;

    #pragma unroll
    for (int k0 = 0; k0 < K; k0 += BK) {
        // A tile: float4 along K, scatter into transposed SMEM
        #pragma unroll
        for (int i = tid; i < BM * BK / 4; i += NT) {
            int r  = i / (BK / 4);
            int c4 = i % (BK / 4);
            int gr = brow + r;
            float4 a = (gr < M) ? *(const float4*)&A[(size_t)gr * K + k0 + c4 * 4]
                                : make_float4(0.f, 0.f, 0.f, 0.f);
            As[c4 * 4 + 0][r] = a.x;
            As[c4 * 4 + 1][r] = a.y;
            As[c4 * 4 + 2][r] = a.z;
            As[c4 * 4 + 3][r] = a.w;
        }
        // B tile: float4 along N, coalesced
        #pragma unroll
        for (int i = tid; i < BK * BN / 4; i += NT) {
            int r  = i / (BN / 4);
            int c4 = i % (BN / 4);
            *(float4*)&Bs[r][c4 * 4] =
                *(const float4*)&B[(size_t)(k0 + r) * N + bcol + c4 * 4];
        }
        __syncthreads();
        #pragma unroll
        for (int k = 0; k < BK; k++) {
            float a[TM], b[TN];
            #pragma unroll
            for (int i = 0; i < TM; i++) a[i] = As[k][trow + i];
            #pragma unroll
            for (int j = 0; j < TN; j++) b[j] = Bs[k][tcol + j];
            #pragma unroll
            for (int i = 0; i < TM; i++)
                #pragma unroll
                for (int j = 0; j < TN; j++)
                    acc[i][j] += a[i] * b[j];
        }
        __syncthreads();
    }

    #pragma unroll
    for (int i = 0; i < TM; i++) {
        int gr = brow + trow + i;
        if (gr >= M) continue;
        if (TN % 4 == 0) {
            #pragma unroll
            for (int j4 = 0; j4 < TN / 4; j4++) {
                float4 v;
                v.x = acc[i][j4 * 4 + 0]; v.y = acc[i][j4 * 4 + 1];
                v.z = acc[i][j4 * 4 + 2]; v.w = acc[i][j4 * 4 + 3];
                if (BIAS) {
                    const float* bp = &bias[bcol + tcol + j4 * 4];
                    v.x += bp[0]; v.y += bp[1]; v.z += bp[2]; v.w += bp[3];
                }
                if (RELU) {
                    v.x = fmaxf(v.x, 0.f); v.y = fmaxf(v.y, 0.f);
                    v.z = fmaxf(v.z, 0.f); v.w = fmaxf(v.w, 0.f);
                }
                *(float4*)&C[(size_t)gr * N + bcol + tcol + j4 * 4] = v;
            }
        } else {
            #pragma unroll
            for (int j = 0; j < TN; j++) {
                float v = acc[i][j];
                if (BIAS) v += bias[bcol + tcol + j];
                if (RELU) v = fmaxf(v, 0.0f);
                C[(size_t)gr * N + bcol + tcol + j] = v;
            }
        }
    }
}

// ---------------- driver -----------------------------------------------------
extern "C" void kernel_launch(void* const* d_in, const int* in_sizes, int n_in,
                              void* d_out, int out_size) {
    const float* x  = (const float*)d_in[0];
    const int*   ei = (const int*)d_in[1];       // int32 (JAX x64 disabled)
    const float* W1 = (const float*)d_in[2];
    const float* b1 = (const float*)d_in[3];
    const float* W2 = (const float*)d_in[4];
    const float* b2 = (const float*)d_in[5];
    const float* W3 = (const float*)d_in[6];
    const float* b3 = (const float*)d_in[7];
    float*       out = (float*)d_out;

    const int n = in_sizes[0] / F_IN;     // 50000
    const int e = in_sizes[1] / 2;        // 800000

    // Real device addresses of __device__ scratch globals.
    float *p_aggx, *p_h1, *p_g2, *p_h2, *p_g3;
    int*   p_count;
    cudaGetSymbolAddress((void**)&p_aggx,  g_aggx);
    cudaGetSymbolAddress((void**)&p_h1,    g_h1);
    cudaGetSymbolAddress((void**)&p_g2,    g_g2);
    cudaGetSymbolAddress((void**)&p_h2,    g_h2);
    cudaGetSymbolAddress((void**)&p_g3,    g_g3);
    cudaGetSymbolAddress((void**)&p_count, g_count);

    // --- graph preprocessing: degree, dinv, CSR-by-dst ---
    cudaMemsetAsync(p_count, 0, (size_t)n * sizeof(int));
    degree_kernel<<<(e + 255) / 256, 256>>>(ei, e);
    dinv_kernel<<<(n + 255) / 256, 256>>>(n);
    int nb = (n + 1023) / 1024;                  // 49 blocks <= 64
    scan_partial_kernel<<<nb, 1024>>>(n);
    scan_bsum_kernel<<<1, 64>>>(nb, n);
    scan_add_kernel<<<nb, 1024>>>(n);
    fill_csr_kernel<<<(e + 255) / 256, 256>>>(ei, e);

    // --- Layer 1: agg(x) then GEMM(128->256) + b1 + relu ---
    agg_kernel<F_IN, false, false><<<(n + 3) / 4, 128>>>(x, nullptr, p_aggx, n);
    {
        dim3 grid(F_H1 / 128, (n + 127) / 128);
        gemm_kernel<128, 128, 16, 8, 8, F_IN, true, true><<<grid, 256>>>(
            p_aggx, W1, b1, p_h1, n, F_H1);
    }

    // --- Layer 2: GEMM(256->128) then agg + b2 + relu ---
    {
        dim3 grid(F_H / 128, (n + 127) / 128);
        gemm_kernel<128, 128, 16, 8, 8, F_H1, false, false><<<grid, 256>>>(
            p_h1, W2, nullptr, p_g2, n, F_H);
    }
    agg_kernel<F_H, true, true><<<(n + 3) / 4, 128>>>(p_g2, b2, p_h2, n);

    // --- Layer 3: GEMM(128->32) then agg + b3 ---
    {
        dim3 grid(F_OUT / 32, (n + 127) / 128);
        gemm_kernel<128, 32, 16, 8, 2, F_H, false, false><<<grid, 256>>>(
            p_h2, W3, nullptr, p_g3, n, F_OUT);
    }
    agg_kernel<F_OUT, true, false><<<(n + 15) / 16, 128>>>(p_g3, b3, out, n);
}

// round 6
// speedup vs baseline: 2.8481x; 1.8102x over previous
#include <cuda_runtime.h>
#include <cuda_bf16.h>
#include <cstdint>

// Problem constants
#define N_NODES 50000
#define N_EDGES 800000
#define F_IN   128
#define F_H1   256
#define F_H    128
#define F_OUT  32
#define M_PAD  50048   // 391 * 128

// ---------------- scratch (static device globals) ---------------------------
__device__ int   g_count [N_NODES];
__device__ float g_dinv  [N_NODES];
__device__ int   g_rowptr[N_NODES + 1];
__device__ int   g_cursor[N_NODES];
__device__ int   g_col   [N_EDGES];
__device__ int   g_bsum  [64];

// bf16 split activation ping-pong buffers (M_PAD rows: GEMM tiles may write
// garbage into rows >= 50000; those rows are never read by the agg kernels)
__device__ __nv_bfloat16 g_s0hi[(size_t)M_PAD * 256];
__device__ __nv_bfloat16 g_s0lo[(size_t)M_PAD * 256];
__device__ __nv_bfloat16 g_s1hi[(size_t)M_PAD * 256];
__device__ __nv_bfloat16 g_s1lo[(size_t)M_PAD * 256];
__device__ float g_g2[(size_t)M_PAD * F_H];
__device__ float g_g3[(size_t)M_PAD * F_OUT];
// transposed + split weights [N][K] (K-major rows)
__device__ __nv_bfloat16 g_w1hi[256 * 128], g_w1lo[256 * 128];
__device__ __nv_bfloat16 g_w2hi[128 * 256], g_w2lo[128 * 256];
__device__ __nv_bfloat16 g_w3hi[32 * 128],  g_w3lo[32 * 128];

// ---------------- PTX helpers (sm_100-base compatible: ldmatrix + mma.sync) --
__device__ __forceinline__ uint32_t smem_u32(const void* p) {
    uint32_t a;
    asm("{ .reg .u64 t; cvta.to.shared.u64 t, %1; cvt.u32.u64 %0, t; }"
        : "=r"(a) : "l"(p));
    return a;
}
__device__ __forceinline__ void ldsm4(uint32_t addr, uint32_t r[4]) {
    asm volatile("ldmatrix.sync.aligned.m8n8.x4.shared.b16 {%0,%1,%2,%3}, [%4];"
                 : "=r"(r[0]), "=r"(r[1]), "=r"(r[2]), "=r"(r[3]) : "r"(addr));
}
__device__ __forceinline__ void ldsm2(uint32_t addr, uint32_t r[2]) {
    asm volatile("ldmatrix.sync.aligned.m8n8.x2.shared.b16 {%0,%1}, [%2];"
                 : "=r"(r[0]), "=r"(r[1]) : "r"(addr));
}
__device__ __forceinline__ void mma16816(float* c, const uint32_t* a, const uint32_t* b) {
    asm volatile(
        "mma.sync.aligned.m16n8k16.row.col.f32.bf16.bf16.f32 "
        "{%0,%1,%2,%3}, {%4,%5,%6,%7}, {%8,%9}, {%0,%1,%2,%3};"
        : "+f"(c[0]), "+f"(c[1]), "+f"(c[2]), "+f"(c[3])
        : "r"(a[0]), "r"(a[1]), "r"(a[2]), "r"(a[3]), "r"(b[0]), "r"(b[1]));
}

// ---------------- graph preprocessing ---------------------------------------
// edge_index int32: [2, E] row-major; src = ei[0:E], dst = ei[E:2E].
__global__ void degree_kernel(const int* __restrict__ ei, int e) {
    int i = blockIdx.x * blockDim.x + threadIdx.x;
    if (i < e) atomicAdd(&g_count[ei[e + i]], 1);
}

__global__ void scan_partial_dinv_kernel(int n) {
    __shared__ int temp[1024];
    int i = blockIdx.x * 1024 + threadIdx.x;
    int v = (i < n) ? g_count[i] : 0;
    if (i < n) g_dinv[i] = rsqrtf((float)(v + 1));  // fused dinv (+1 self-loop)
    temp[threadIdx.x] = v;
    __syncthreads();
    #pragma unroll
    for (int off = 1; off < 1024; off <<= 1) {
        int t = (threadIdx.x >= off) ? temp[threadIdx.x - off] : 0;
        __syncthreads();
        temp[threadIdx.x] += t;
        __syncthreads();
    }
    if (i < n) g_rowptr[i] = temp[threadIdx.x] - v;  // local exclusive
    if (threadIdx.x == 1023) g_bsum[blockIdx.x] = temp[1023];
}

__global__ void scan_bsum_kernel(int nb, int n) {
    __shared__ int t[64];
    int v = (threadIdx.x < nb) ? g_bsum[threadIdx.x] : 0;
    t[threadIdx.x] = v;
    __syncthreads();
    #pragma unroll
    for (int off = 1; off < 64; off <<= 1) {
        int u = (threadIdx.x >= off) ? t[threadIdx.x - off] : 0;
        __syncthreads();
        t[threadIdx.x] += u;
        __syncthreads();
    }
    if (threadIdx.x < nb) g_bsum[threadIdx.x] = t[threadIdx.x] - v;
    if (threadIdx.x == 63) g_rowptr[n] = t[63];
}

__global__ void scan_add_kernel(int n) {
    int i = blockIdx.x * 1024 + threadIdx.x;
    if (i < n) {
        int v = g_rowptr[i] + g_bsum[blockIdx.x];
        g_rowptr[i] = v;
        g_cursor[i] = v;
    }
}

__global__ void fill_csr_kernel(const int* __restrict__ ei, int e) {
    int i = blockIdx.x * blockDim.x + threadIdx.x;
    if (i < e) {
        int src = ei[i];
        int dst = ei[e + i];
        int pos = atomicAdd(&g_cursor[dst], 1);
        g_col[pos] = src;
    }
}

__global__ void zero_count_kernel(int n) {
    int i = blockIdx.x * blockDim.x + threadIdx.x;
    if (i < n) g_count[i] = 0;   // reset for next graph replay
}

// ---------------- pull aggregation (float4), optional bf16-split output -----
template <int F, bool BIAS, bool RELU, bool SPLIT>
__global__ void agg_kernel(const float* __restrict__ g,
                           const float* __restrict__ bias,
                           float* __restrict__ outf,
                           __nv_bfloat16* __restrict__ oh,
                           __nv_bfloat16* __restrict__ ol, int n) {
    constexpr int TPN = F / 4;
    int npb  = blockDim.x / TPN;
    int node = blockIdx.x * npb + threadIdx.x / TPN;
    if (node >= n) return;
    int lane = threadIdx.x % TPN;

    const float4* gv = (const float4*)g;
    float di = g_dinv[node];
    float4 s = gv[(size_t)node * TPN + lane];
    float4 acc = make_float4(di * s.x, di * s.y, di * s.z, di * s.w);

    int e  = g_rowptr[node];
    int e1 = g_rowptr[node + 1];
    for (; e + 4 <= e1; e += 4) {
        int s0 = g_col[e], s1 = g_col[e + 1], s2 = g_col[e + 2], s3 = g_col[e + 3];
        float d0 = g_dinv[s0], d1 = g_dinv[s1], d2 = g_dinv[s2], d3 = g_dinv[s3];
        float4 v0 = gv[(size_t)s0 * TPN + lane];
        float4 v1 = gv[(size_t)s1 * TPN + lane];
        float4 v2 = gv[(size_t)s2 * TPN + lane];
        float4 v3 = gv[(size_t)s3 * TPN + lane];
        acc.x += d0 * v0.x + d1 * v1.x + d2 * v2.x + d3 * v3.x;
        acc.y += d0 * v0.y + d1 * v1.y + d2 * v2.y + d3 * v3.y;
        acc.z += d0 * v0.z + d1 * v1.z + d2 * v2.z + d3 * v3.z;
        acc.w += d0 * v0.w + d1 * v1.w + d2 * v2.w + d3 * v3.w;
    }
    for (; e < e1; e++) {
        int sv = g_col[e];
        float d = g_dinv[sv];
        float4 v = gv[(size_t)sv * TPN + lane];
        acc.x += d * v.x; acc.y += d * v.y; acc.z += d * v.z; acc.w += d * v.w;
    }
    acc.x *= di; acc.y *= di; acc.z *= di; acc.w *= di;
    if (BIAS) {
        float4 b = ((const float4*)bias)[lane];
        acc.x += b.x; acc.y += b.y; acc.z += b.z; acc.w += b.w;
    }
    if (RELU) {
        acc.x = fmaxf(acc.x, 0.f); acc.y = fmaxf(acc.y, 0.f);
        acc.z = fmaxf(acc.z, 0.f); acc.w = fmaxf(acc.w, 0.f);
    }
    if constexpr (SPLIT) {
        size_t o = (size_t)node * F + lane * 4;
        __nv_bfloat16 h0 = __float2bfloat16(acc.x);
        __nv_bfloat16 h1 = __float2bfloat16(acc.y);
        __nv_bfloat16 h2 = __float2bfloat16(acc.z);
        __nv_bfloat16 h3 = __float2bfloat16(acc.w);
        __nv_bfloat16 l0 = __float2bfloat16(acc.x - __bfloat162float(h0));
        __nv_bfloat16 l1 = __float2bfloat16(acc.y - __bfloat162float(h1));
        __nv_bfloat16 l2 = __float2bfloat16(acc.z - __bfloat162float(h2));
        __nv_bfloat16 l3 = __float2bfloat16(acc.w - __bfloat162float(h3));
        *reinterpret_cast<__nv_bfloat162*>(oh + o)     = __halves2bfloat162(h0, h1);
        *reinterpret_cast<__nv_bfloat162*>(oh + o + 2) = __halves2bfloat162(h2, h3);
        *reinterpret_cast<__nv_bfloat162*>(ol + o)     = __halves2bfloat162(l0, l1);
        *reinterpret_cast<__nv_bfloat162*>(ol + o + 2) = __halves2bfloat162(l2, l3);
    } else {
        ((float4*)outf)[(size_t)node * TPN + lane] = acc;
    }
}

// ---------------- weight transpose + bf16 split (all 3 layers, 1 launch) ----
__global__ void splitW_all(const float* __restrict__ W1, const float* __restrict__ W2,
                           const float* __restrict__ W3,
                           __nv_bfloat16* w1h, __nv_bfloat16* w1l,
                           __nv_bfloat16* w2h, __nv_bfloat16* w2l,
                           __nv_bfloat16* w3h, __nv_bfloat16* w3l) {
    int idx = blockIdx.x * blockDim.x + threadIdx.x;
    float v; __nv_bfloat16* ph; __nv_bfloat16* pl; int o;
    if (idx < 256 * 128) {                       // W1 [128,256] -> [256][128]
        int nn = idx / 128, k = idx % 128;
        v = W1[k * 256 + nn]; ph = w1h; pl = w1l; o = idx;
    } else if (idx < 256 * 128 + 128 * 256) {    // W2 [256,128] -> [128][256]
        int i2 = idx - 256 * 128;
        int nn = i2 / 256, k = i2 % 256;
        v = W2[k * 128 + nn]; ph = w2h; pl = w2l; o = i2;
    } else if (idx < 256 * 128 + 128 * 256 + 32 * 128) {  // W3 [128,32] -> [32][128]
        int i3 = idx - 256 * 128 - 128 * 256;
        int nn = i3 / 128, k = i3 % 128;
        v = W3[k * 32 + nn]; ph = w3h; pl = w3l; o = i3;
    } else return;
    __nv_bfloat16 h = __float2bfloat16(v);
    ph[o] = h;
    pl[o] = __float2bfloat16(v - __bfloat162float(h));
}

// ---------------- mma.sync bf16-split GEMM ----------------------------------
// C[M, Ntotal] = A[M, K] @ B^T with B stored [Ntotal][K] (K-major rows).
// Block tile BM=128 x NB.  A ~ Ahi+Alo, B ~ Bhi+Blo; D += AhBh + AhBl + AlBh.
// Warps tiled WARPS_M x WARPS_N; per-warp WM=128/WARPS_M, WN=NB/WARPS_N.
template <int NB, int K, int WARPS_M, int WARPS_N, bool BIAS, bool RELU, bool SPLIT_OUT>
__global__ __launch_bounds__(32 * WARPS_M * WARPS_N)
void gemm_mma(const __nv_bfloat16* __restrict__ Ahi, const __nv_bfloat16* __restrict__ Alo,
              const __nv_bfloat16* __restrict__ Bhi, const __nv_bfloat16* __restrict__ Blo,
              const float* __restrict__ bias,
              float* __restrict__ Cf, __nv_bfloat16* __restrict__ Chi,
              __nv_bfloat16* __restrict__ Clo, int M, int Ntotal) {
    constexpr int BM  = 128;
    constexpr int KC  = 64;           // K per smem chunk
    constexpr int LDS = KC + 8;       // row pad -> conflict-free ldmatrix
    constexpr int NT  = 32 * WARPS_M * WARPS_N;
    constexpr int WM  = BM / WARPS_M;
    constexpr int WN  = NB / WARPS_N;
    constexpr int MF  = WM / 16;      // 16-row m-frags per warp
    constexpr int NF  = WN / 8;       // 8-col n-frags per warp

    extern __shared__ __nv_bfloat16 sm[];
    __nv_bfloat16* sAh = sm;
    __nv_bfloat16* sAl = sAh + BM * LDS;
    __nv_bfloat16* sBh = sAl + BM * LDS;
    __nv_bfloat16* sBl = sBh + NB * LDS;
    uint32_t uAh = smem_u32(sAh), uAl = smem_u32(sAl);
    uint32_t uBh = smem_u32(sBh), uBl = smem_u32(sBl);

    int tid  = threadIdx.x;
    int wid  = tid >> 5, lane = tid & 31;
    int wm0  = (wid / WARPS_N) * WM;
    int wn0  = (wid % WARPS_N) * WN;
    int m0   = blockIdx.x * BM;
    int n0   = blockIdx.y * NB;

    // per-lane ldmatrix offsets
    int a_r = lane & 15, a_c = (lane >> 4) * 8;        // x4 (A)
    int b_r = lane & 7,  b_c = ((lane >> 3) & 1) * 8;  // x2 (B)

    float acc[MF][NF][4];
    #pragma unroll
    for (int i = 0; i < MF; i++)
        #pragma unroll
        for (int j = 0; j < NF; j++)
            #pragma unroll
            for (int q = 0; q < 4; q++) acc[i][j][q] = 0.0f;

    #pragma unroll
    for (int ch = 0; ch < K / KC; ch++) {
        int kc = ch * KC;
        if (ch > 0) __syncthreads();
        // A chunk: 128 rows x 8 x 16B per matrix (hi & lo)
        for (int i = tid; i < BM * 8; i += NT) {
            int r = i >> 3, c = i & 7;
            size_t go = (size_t)(m0 + r) * K + kc + c * 8;
            *(uint4*)(sAh + r * LDS + c * 8) = *(const uint4*)(Ahi + go);
            *(uint4*)(sAl + r * LDS + c * 8) = *(const uint4*)(Alo + go);
        }
        // B chunk: NB rows x 8 x 16B
        for (int i = tid; i < NB * 8; i += NT) {
            int r = i >> 3, c = i & 7;
            size_t go = (size_t)(n0 + r) * K + kc + c * 8;
            *(uint4*)(sBh + r * LDS + c * 8) = *(const uint4*)(Bhi + go);
            *(uint4*)(sBl + r * LDS + c * 8) = *(const uint4*)(Blo + go);
        }
        __syncthreads();

        #pragma unroll
        for (int ks = 0; ks < KC / 16; ks++) {
            int k0 = ks * 16;
            uint32_t ah[MF][4], al[MF][4], bh[NF][2], bl[NF][2];
            #pragma unroll
            for (int i = 0; i < MF; i++) {
                uint32_t off = (uint32_t)((wm0 + i * 16 + a_r) * LDS + k0 + a_c) * 2;
                ldsm4(uAh + off, ah[i]);
                ldsm4(uAl + off, al[i]);
            }
            #pragma unroll
            for (int j = 0; j < NF; j++) {
                uint32_t off = (uint32_t)((wn0 + j * 8 + b_r) * LDS + k0 + b_c) * 2;
                ldsm2(uBh + off, bh[j]);
                ldsm2(uBl + off, bl[j]);
            }
            #pragma unroll
            for (int i = 0; i < MF; i++)
                #pragma unroll
                for (int j = 0; j < NF; j++) {
                    mma16816(acc[i][j], ah[i], bh[j]);
                    mma16816(acc[i][j], ah[i], bl[j]);
                    mma16816(acc[i][j], al[i], bh[j]);
                }
        }
    }

    // ---- epilogue: registers -> C with fused bias/relu (+optional split) ----
    int g = lane >> 2, t = lane & 3;
    #pragma unroll
    for (int i = 0; i < MF; i++) {
        #pragma unroll
        for (int j = 0; j < NF; j++) {
            int col = n0 + wn0 + j * 8 + 2 * t;
            #pragma unroll
            for (int h = 0; h < 2; h++) {           // h=0: rows g, h=1: rows g+8
                int row = m0 + wm0 + i * 16 + g + h * 8;
                float v0 = acc[i][j][h * 2 + 0];
                float v1 = acc[i][j][h * 2 + 1];
                if (BIAS) { v0 += bias[col]; v1 += bias[col + 1]; }
                if (RELU) { v0 = fmaxf(v0, 0.f); v1 = fmaxf(v1, 0.f); }
                if constexpr (SPLIT_OUT) {
                    __nv_bfloat16 h0 = __float2bfloat16(v0);
                    __nv_bfloat16 h1 = __float2bfloat16(v1);
                    __nv_bfloat16 l0 = __float2bfloat16(v0 - __bfloat162float(h0));
                    __nv_bfloat16 l1 = __float2bfloat16(v1 - __bfloat162float(h1));
                    size_t off = (size_t)row * Ntotal + col;
                    *reinterpret_cast<__nv_bfloat162*>(Chi + off) = __halves2bfloat162(h0, h1);
                    *reinterpret_cast<__nv_bfloat162*>(Clo + off) = __halves2bfloat162(l0, l1);
                } else {
                    *reinterpret_cast<float2*>(Cf + (size_t)row * Ntotal + col) =
                        make_float2(v0, v1);
                }
            }
        }
    }
}

// ---------------- driver -----------------------------------------------------
extern "C" void kernel_launch(void* const* d_in, const int* in_sizes, int n_in,
                              void* d_out, int out_size) {
    const float* x  = (const float*)d_in[0];
    const int*   ei = (const int*)d_in[1];       // int32 (JAX x64 disabled)
    const float* W1 = (const float*)d_in[2];
    const float* b1 = (const float*)d_in[3];
    const float* W2 = (const float*)d_in[4];
    const float* b2 = (const float*)d_in[5];
    const float* W3 = (const float*)d_in[6];
    const float* b3 = (const float*)d_in[7];
    float*       out = (float*)d_out;

    const int n = in_sizes[0] / F_IN;   // 50000
    const int e = in_sizes[1] / 2;      // 800000

    // Real device addresses of scratch globals.
    __nv_bfloat16 *s0h, *s0l, *s1h, *s1l, *w1h, *w1l, *w2h, *w2l, *w3h, *w3l;
    float *p_g2, *p_g3;
    cudaGetSymbolAddress((void**)&s0h, g_s0hi);
    cudaGetSymbolAddress((void**)&s0l, g_s0lo);
    cudaGetSymbolAddress((void**)&s1h, g_s1hi);
    cudaGetSymbolAddress((void**)&s1l, g_s1lo);
    cudaGetSymbolAddress((void**)&w1h, g_w1hi);
    cudaGetSymbolAddress((void**)&w1l, g_w1lo);
    cudaGetSymbolAddress((void**)&w2h, g_w2hi);
    cudaGetSymbolAddress((void**)&w2l, g_w2lo);
    cudaGetSymbolAddress((void**)&w3h, g_w3hi);
    cudaGetSymbolAddress((void**)&w3l, g_w3lo);
    cudaGetSymbolAddress((void**)&p_g2, g_g2);
    cudaGetSymbolAddress((void**)&p_g3, g_g3);

    // Dynamic smem sizes: (2*128 + 2*NB) * (64+8) * 2 bytes
    const int smem128 = (2 * 128 + 2 * 128) * 72 * 2;  // 73728
    const int smem32  = (2 * 128 + 2 * 32)  * 72 * 2;  // 46080
    cudaFuncSetAttribute(gemm_mma<128, 128, 4, 2, true,  true,  true >,
                         cudaFuncAttributeMaxDynamicSharedMemorySize, smem128);
    cudaFuncSetAttribute(gemm_mma<128, 256, 4, 2, false, false, false>,
                         cudaFuncAttributeMaxDynamicSharedMemorySize, smem128);
    cudaFuncSetAttribute(gemm_mma<32,  128, 8, 1, false, false, false>,
                         cudaFuncAttributeMaxDynamicSharedMemorySize, smem32);

    const int mt = M_PAD / 128;         // 391 row tiles
    const int nb = (n + 1023) / 1024;   // scan blocks (49)

    // --- preprocessing (count starts zero: zero-init'd + re-zeroed at end) ---
    degree_kernel<<<(e + 255) / 256, 256>>>(ei, e);
    scan_partial_dinv_kernel<<<nb, 1024>>>(n);
    scan_bsum_kernel<<<1, 64>>>(nb, n);
    scan_add_kernel<<<nb, 1024>>>(n);
    fill_csr_kernel<<<(e + 255) / 256, 256>>>(ei, e);

    // --- Layer 1: agg(x) -> split bf16; mma-GEMM(128->256)+b1+relu -> split --
    agg_kernel<F_IN, false, false, true><<<(n + 3) / 4, 128>>>(
        x, nullptr, nullptr, s0h, s0l, n);
    splitW_all<<<(256 * 128 + 128 * 256 + 32 * 128 + 255) / 256, 256>>>(
        W1, W2, W3, w1h, w1l, w2h, w2l, w3h, w3l);
    {
        dim3 grid(mt, 2);
        gemm_mma<128, 128, 4, 2, true, true, true><<<grid, 256, smem128>>>(
            s0h, s0l, w1h, w1l, b1, nullptr, s1h, s1l, n, F_H1);
    }

    // --- Layer 2: mma-GEMM(256->128) -> fp32; agg+b2+relu -> split ---
    {
        dim3 grid(mt, 1);
        gemm_mma<128, 256, 4, 2, false, false, false><<<grid, 256, smem128>>>(
            s1h, s1l, w2h, w2l, nullptr, p_g2, nullptr, nullptr, n, F_H);
    }
    agg_kernel<F_H, true, true, true><<<(n + 3) / 4, 128>>>(
        p_g2, b2, nullptr, s0h, s0l, n);

    // --- Layer 3: mma-GEMM(128->32) -> fp32; agg+b3 -> out ---
    {
        dim3 grid(mt, 1);
        gemm_mma<32, 128, 8, 1, false, false, false><<<grid, 256, smem32>>>(
            s0h, s0l, w3h, w3l, nullptr, p_g3, nullptr, nullptr, n, F_OUT);
    }
    agg_kernel<F_OUT, true, false, false><<<(n + 15) / 16, 128>>>(
        p_g3, b3, out, nullptr, nullptr, n);

    zero_count_kernel<<<(n + 1023) / 1024, 1024>>>(n);
}

// round 7
// speedup vs baseline: 3.2479x; 1.1404x over previous
#include <cuda_runtime.h>
#include <cuda_bf16.h>
#include <cstdint>

// Problem constants
#define N_NODES 50000
#define N_EDGES 800000
#define F_IN   128
#define F_H1   256
#define F_H    128
#define F_OUT  32
#define M_PAD  50048   // 391 * 128

// ---------------- scratch (static device globals) ---------------------------
__device__ int   g_count [N_NODES];
__device__ float g_dinv  [M_PAD];        // rows >= N_NODES stay 0 (never written)
__device__ int   g_rowptr[N_NODES + 1];
__device__ int   g_cursor[N_NODES];
__device__ int   g_col   [N_EDGES];
__device__ int   g_bsum  [64];

// bf16 split activation ping-pong buffers (pad rows >= 50000 are only ever
// functions of zeros -> deterministic; never read by agg kernels)
__device__ __nv_bfloat16 g_s0hi[(size_t)M_PAD * 256];
__device__ __nv_bfloat16 g_s0lo[(size_t)M_PAD * 256];
__device__ __nv_bfloat16 g_s1hi[(size_t)M_PAD * 256];
__device__ __nv_bfloat16 g_s1lo[(size_t)M_PAD * 256];
__device__ float g_g2[(size_t)M_PAD * F_H];
__device__ float g_g3[(size_t)M_PAD * F_OUT];
// transposed + split weights [N][K] (K-major rows)
__device__ __nv_bfloat16 g_w1hi[256 * 128], g_w1lo[256 * 128];
__device__ __nv_bfloat16 g_w2hi[128 * 256], g_w2lo[128 * 256];
__device__ __nv_bfloat16 g_w3hi[32 * 128],  g_w3lo[32 * 128];

// ---------------- PTX helpers ------------------------------------------------
__device__ __forceinline__ uint32_t smem_u32(const void* p) {
    uint32_t a;
    asm("{ .reg .u64 t; cvta.to.shared.u64 t, %1; cvt.u32.u64 %0, t; }"
        : "=r"(a) : "l"(p));
    return a;
}
__device__ __forceinline__ void ldsm4(uint32_t addr, uint32_t r[4]) {
    asm volatile("ldmatrix.sync.aligned.m8n8.x4.shared.b16 {%0,%1,%2,%3}, [%4];"
                 : "=r"(r[0]), "=r"(r[1]), "=r"(r[2]), "=r"(r[3]) : "r"(addr));
}
__device__ __forceinline__ void ldsm2(uint32_t addr, uint32_t r[2]) {
    asm volatile("ldmatrix.sync.aligned.m8n8.x2.shared.b16 {%0,%1}, [%2];"
                 : "=r"(r[0]), "=r"(r[1]) : "r"(addr));
}
__device__ __forceinline__ void mma16816(float* c, const uint32_t* a, const uint32_t* b) {
    asm volatile(
        "mma.sync.aligned.m16n8k16.row.col.f32.bf16.bf16.f32 "
        "{%0,%1,%2,%3}, {%4,%5,%6,%7}, {%8,%9}, {%0,%1,%2,%3};"
        : "+f"(c[0]), "+f"(c[1]), "+f"(c[2]), "+f"(c[3])
        : "r"(a[0]), "r"(a[1]), "r"(a[2]), "r"(a[3]), "r"(b[0]), "r"(b[1]));
}
__device__ __forceinline__ void cp16(uint32_t saddr, const void* gaddr) {
    asm volatile("cp.async.cg.shared.global [%0], [%1], 16;"
                 :: "r"(saddr), "l"(gaddr));
}
#define CP_COMMIT() asm volatile("cp.async.commit_group;" ::: "memory")

// ---------------- graph preprocessing ---------------------------------------
// edge_index int32: [2, E] row-major; src = ei[0:E], dst = ei[E:2E].
__global__ void degree_kernel(const int* __restrict__ ei, int e) {
    int i = blockIdx.x * blockDim.x + threadIdx.x;
    if (i < e) atomicAdd(&g_count[ei[e + i]], 1);
}

__global__ void scan_partial_dinv_kernel(int n) {
    __shared__ int temp[1024];
    int i = blockIdx.x * 1024 + threadIdx.x;
    int v = (i < n) ? g_count[i] : 0;
    if (i < n) g_dinv[i] = rsqrtf((float)(v + 1));  // fused dinv (+1 self-loop)
    temp[threadIdx.x] = v;
    __syncthreads();
    #pragma unroll
    for (int off = 1; off < 1024; off <<= 1) {
        int t = (threadIdx.x >= off) ? temp[threadIdx.x - off] : 0;
        __syncthreads();
        temp[threadIdx.x] += t;
        __syncthreads();
    }
    if (i < n) g_rowptr[i] = temp[threadIdx.x] - v;  // local exclusive
    if (threadIdx.x == 1023) g_bsum[blockIdx.x] = temp[1023];
}

__global__ void scan_bsum_kernel(int nb, int n) {
    __shared__ int t[64];
    int v = (threadIdx.x < nb) ? g_bsum[threadIdx.x] : 0;
    t[threadIdx.x] = v;
    __syncthreads();
    #pragma unroll
    for (int off = 1; off < 64; off <<= 1) {
        int u = (threadIdx.x >= off) ? t[threadIdx.x - off] : 0;
        __syncthreads();
        t[threadIdx.x] += u;
        __syncthreads();
    }
    if (threadIdx.x < nb) g_bsum[threadIdx.x] = t[threadIdx.x] - v;
    if (threadIdx.x == 63) g_rowptr[n] = t[63];
}

__global__ void scan_add_kernel(int n) {
    int i = blockIdx.x * 1024 + threadIdx.x;
    if (i < n) {
        int v = g_rowptr[i] + g_bsum[blockIdx.x];
        g_rowptr[i] = v;
        g_cursor[i] = v;
        g_count[i]  = 0;   // reset for next replay (count no longer needed)
    }
}

__global__ void fill_csr_kernel(const int* __restrict__ ei, int e) {
    int i = blockIdx.x * blockDim.x + threadIdx.x;
    if (i < e) {
        int src = ei[i];
        int dst = ei[e + i];
        int pos = atomicAdd(&g_cursor[dst], 1);
        g_col[pos] = src;
    }
}

// ---------------- pull aggregation (float4, unroll 8) ------------------------
// PRESCALED: g rows already carry dinv[src] (folded into GEMM epilogue);
//            out[d] = dinv[d]*(sum g'[s] + g'[d]) (+bias)(relu)
// else:      out[d] = dinv[d]*(sum dinv[s]*g[s] + dinv[d]*g[d]) (+bias)(relu)
template <int F, bool BIAS, bool RELU, bool SPLIT, bool PRESCALED>
__global__ void agg_kernel(const float* __restrict__ g,
                           const float* __restrict__ bias,
                           float* __restrict__ outf,
                           __nv_bfloat16* __restrict__ oh,
                           __nv_bfloat16* __restrict__ ol, int n) {
    constexpr int TPN = F / 4;
    int npb  = blockDim.x / TPN;
    int node = blockIdx.x * npb + threadIdx.x / TPN;
    if (node >= n) return;
    int lane = threadIdx.x % TPN;

    const float4* gv = (const float4*)g;
    float di = g_dinv[node];
    float4 s = gv[(size_t)node * TPN + lane];
    float4 acc;
    if (PRESCALED) acc = s;                                     // g'[d] = di*g[d]
    else           acc = make_float4(di * s.x, di * s.y, di * s.z, di * s.w);

    int e  = g_rowptr[node];
    int e1 = g_rowptr[node + 1];
    for (; e + 8 <= e1; e += 8) {
        int   c[8];
        float4 v[8];
        #pragma unroll
        for (int j = 0; j < 8; j++) c[j] = g_col[e + j];
        #pragma unroll
        for (int j = 0; j < 8; j++) v[j] = gv[(size_t)c[j] * TPN + lane];
        if (!PRESCALED) {
            #pragma unroll
            for (int j = 0; j < 8; j++) {
                float d = g_dinv[c[j]];
                v[j].x *= d; v[j].y *= d; v[j].z *= d; v[j].w *= d;
            }
        }
        #pragma unroll
        for (int j = 0; j < 8; j++) {
            acc.x += v[j].x; acc.y += v[j].y; acc.z += v[j].z; acc.w += v[j].w;
        }
    }
    for (; e < e1; e++) {
        int sv = g_col[e];
        float4 v = gv[(size_t)sv * TPN + lane];
        float d = PRESCALED ? 1.0f : g_dinv[sv];
        acc.x += d * v.x; acc.y += d * v.y; acc.z += d * v.z; acc.w += d * v.w;
    }
    acc.x *= di; acc.y *= di; acc.z *= di; acc.w *= di;
    if (BIAS) {
        float4 b = ((const float4*)bias)[lane];
        acc.x += b.x; acc.y += b.y; acc.z += b.z; acc.w += b.w;
    }
    if (RELU) {
        acc.x = fmaxf(acc.x, 0.f); acc.y = fmaxf(acc.y, 0.f);
        acc.z = fmaxf(acc.z, 0.f); acc.w = fmaxf(acc.w, 0.f);
    }
    if constexpr (SPLIT) {
        size_t o = (size_t)node * F + lane * 4;
        __nv_bfloat16 h0 = __float2bfloat16(acc.x);
        __nv_bfloat16 h1 = __float2bfloat16(acc.y);
        __nv_bfloat16 h2 = __float2bfloat16(acc.z);
        __nv_bfloat16 h3 = __float2bfloat16(acc.w);
        __nv_bfloat16 l0 = __float2bfloat16(acc.x - __bfloat162float(h0));
        __nv_bfloat16 l1 = __float2bfloat16(acc.y - __bfloat162float(h1));
        __nv_bfloat16 l2 = __float2bfloat16(acc.z - __bfloat162float(h2));
        __nv_bfloat16 l3 = __float2bfloat16(acc.w - __bfloat162float(h3));
        *reinterpret_cast<__nv_bfloat162*>(oh + o)     = __halves2bfloat162(h0, h1);
        *reinterpret_cast<__nv_bfloat162*>(oh + o + 2) = __halves2bfloat162(h2, h3);
        *reinterpret_cast<__nv_bfloat162*>(ol + o)     = __halves2bfloat162(l0, l1);
        *reinterpret_cast<__nv_bfloat162*>(ol + o + 2) = __halves2bfloat162(l2, l3);
    } else {
        ((float4*)outf)[(size_t)node * TPN + lane] = acc;
    }
}

// ---------------- weight transpose + bf16 split (all 3 layers, 1 launch) ----
__global__ void splitW_all(const float* __restrict__ W1, const float* __restrict__ W2,
                           const float* __restrict__ W3,
                           __nv_bfloat16* w1h, __nv_bfloat16* w1l,
                           __nv_bfloat16* w2h, __nv_bfloat16* w2l,
                           __nv_bfloat16* w3h, __nv_bfloat16* w3l) {
    int idx = blockIdx.x * blockDim.x + threadIdx.x;
    float v; __nv_bfloat16* ph; __nv_bfloat16* pl; int o;
    if (idx < 256 * 128) {                       // W1 [128,256] -> [256][128]
        int nn = idx / 128, k = idx % 128;
        v = W1[k * 256 + nn]; ph = w1h; pl = w1l; o = idx;
    } else if (idx < 256 * 128 + 128 * 256) {    // W2 [256,128] -> [128][256]
        int i2 = idx - 256 * 128;
        int nn = i2 / 256, k = i2 % 256;
        v = W2[k * 128 + nn]; ph = w2h; pl = w2l; o = i2;
    } else if (idx < 256 * 128 + 128 * 256 + 32 * 128) {  // W3 [128,32] -> [32][128]
        int i3 = idx - 256 * 128 - 128 * 256;
        int nn = i3 / 128, k = i3 % 128;
        v = W3[k * 32 + nn]; ph = w3h; pl = w3l; o = i3;
    } else return;
    __nv_bfloat16 h = __float2bfloat16(v);
    ph[o] = h;
    pl[o] = __float2bfloat16(v - __bfloat162float(h));
}

// ---------------- mma.sync bf16-split GEMM, cp.async double-buffered --------
// C[M, Ntotal] = A[M, K] @ B^T, B stored [Ntotal][K] (K-major rows).
// D += AhBh + AhBl + AlBh; optional epilogue dinv[row] prescale (DINV).
template <int NB, int K, int WARPS_M, int WARPS_N, bool BIAS, bool RELU,
          bool SPLIT_OUT, bool DINV>
__global__ __launch_bounds__(32 * WARPS_M * WARPS_N)
void gemm_mma(const __nv_bfloat16* __restrict__ Ahi, const __nv_bfloat16* __restrict__ Alo,
              const __nv_bfloat16* __restrict__ Bhi, const __nv_bfloat16* __restrict__ Blo,
              const float* __restrict__ bias,
              float* __restrict__ Cf, __nv_bfloat16* __restrict__ Chi,
              __nv_bfloat16* __restrict__ Clo, int M, int Ntotal) {
    constexpr int BM  = 128;
    constexpr int KC  = 32;           // K per chunk
    constexpr int LDS = KC + 8;       // 40: conflict-free ldmatrix
    constexpr int NT  = 32 * WARPS_M * WARPS_N;
    constexpr int WM  = BM / WARPS_M;
    constexpr int WN  = NB / WARPS_N;
    constexpr int MF  = WM / 16;
    constexpr int NF  = WN / 8;
    constexpr int NCH = K / KC;
    constexpr int C8  = KC / 8;       // 4 cp16 per row
    // per-stage element offsets
    constexpr int AOFF_H = 0;
    constexpr int AOFF_L = BM * LDS;
    constexpr int BOFF_H = 2 * BM * LDS;
    constexpr int BOFF_L = 2 * BM * LDS + NB * LDS;
    constexpr int SSZ    = (2 * BM + 2 * NB) * LDS;   // elements per stage

    extern __shared__ __nv_bfloat16 sm[];
    uint32_t u0 = smem_u32(sm);

    int tid  = threadIdx.x;
    int wid  = tid >> 5, lane = tid & 31;
    int wm0  = (wid / WARPS_N) * WM;
    int wn0  = (wid % WARPS_N) * WN;
    int m0   = blockIdx.x * BM;
    int n0   = blockIdx.y * NB;

    int a_r = lane & 15, a_c = (lane >> 4) * 8;        // ldmatrix x4 (A)
    int b_r = lane & 7,  b_c = ((lane >> 3) & 1) * 8;  // ldmatrix x2 (B)

    float acc[MF][NF][4];
    #pragma unroll
    for (int i = 0; i < MF; i++)
        #pragma unroll
        for (int j = 0; j < NF; j++)
            #pragma unroll
            for (int q = 0; q < 4; q++) acc[i][j][q] = 0.0f;

    auto issue = [&](int ch, int st) {
        int kc = ch * KC;
        uint32_t ub = u0 + (uint32_t)st * SSZ * 2;
        for (int i = tid; i < BM * C8; i += NT) {
            int r = i / C8, c = i % C8;
            uint32_t so = (uint32_t)(r * LDS + c * 8) * 2;
            size_t go = (size_t)(m0 + r) * K + kc + c * 8;
            cp16(ub + AOFF_H * 2 + so, Ahi + go);
            cp16(ub + AOFF_L * 2 + so, Alo + go);
        }
        for (int i = tid; i < NB * C8; i += NT) {
            int r = i / C8, c = i % C8;
            uint32_t so = (uint32_t)(r * LDS + c * 8) * 2;
            size_t go = (size_t)(n0 + r) * K + kc + c * 8;
            cp16(ub + BOFF_H * 2 + so, Bhi + go);
            cp16(ub + BOFF_L * 2 + so, Blo + go);
        }
        CP_COMMIT();
    };

    issue(0, 0);
    #pragma unroll
    for (int ch = 0; ch < NCH; ch++) {
        if (ch + 1 < NCH) {
            issue(ch + 1, (ch + 1) & 1);
            asm volatile("cp.async.wait_group 1;" ::: "memory");
        } else {
            asm volatile("cp.async.wait_group 0;" ::: "memory");
        }
        __syncthreads();

        uint32_t ub = u0 + (uint32_t)(ch & 1) * SSZ * 2;
        #pragma unroll
        for (int ks = 0; ks < KC / 16; ks++) {
            int k0 = ks * 16;
            uint32_t ah[MF][4], al[MF][4], bh[NF][2], bl[NF][2];
            #pragma unroll
            for (int i = 0; i < MF; i++) {
                uint32_t off = (uint32_t)((wm0 + i * 16 + a_r) * LDS + k0 + a_c) * 2;
                ldsm4(ub + AOFF_H * 2 + off, ah[i]);
                ldsm4(ub + AOFF_L * 2 + off, al[i]);
            }
            #pragma unroll
            for (int j = 0; j < NF; j++) {
                uint32_t off = (uint32_t)((wn0 + j * 8 + b_r) * LDS + k0 + b_c) * 2;
                ldsm2(ub + BOFF_H * 2 + off, bh[j]);
                ldsm2(ub + BOFF_L * 2 + off, bl[j]);
            }
            #pragma unroll
            for (int i = 0; i < MF; i++)
                #pragma unroll
                for (int j = 0; j < NF; j++) {
                    mma16816(acc[i][j], ah[i], bh[j]);
                    mma16816(acc[i][j], ah[i], bl[j]);
                    mma16816(acc[i][j], al[i], bh[j]);
                }
        }
        __syncthreads();
    }

    // ---- epilogue: registers -> C with fused bias/relu/dinv (+split) ----
    int gr = lane >> 2, t = lane & 3;
    #pragma unroll
    for (int i = 0; i < MF; i++) {
        #pragma unroll
        for (int j = 0; j < NF; j++) {
            int col = n0 + wn0 + j * 8 + 2 * t;
            #pragma unroll
            for (int h = 0; h < 2; h++) {
                int row = m0 + wm0 + i * 16 + gr + h * 8;
                float v0 = acc[i][j][h * 2 + 0];
                float v1 = acc[i][j][h * 2 + 1];
                if (BIAS) { v0 += bias[col]; v1 += bias[col + 1]; }
                if (RELU) { v0 = fmaxf(v0, 0.f); v1 = fmaxf(v1, 0.f); }
                if (DINV) { float d = g_dinv[row]; v0 *= d; v1 *= d; }
                if constexpr (SPLIT_OUT) {
                    __nv_bfloat16 h0 = __float2bfloat16(v0);
                    __nv_bfloat16 h1 = __float2bfloat16(v1);
                    __nv_bfloat16 l0 = __float2bfloat16(v0 - __bfloat162float(h0));
                    __nv_bfloat16 l1 = __float2bfloat16(v1 - __bfloat162float(h1));
                    size_t off = (size_t)row * Ntotal + col;
                    *reinterpret_cast<__nv_bfloat162*>(Chi + off) = __halves2bfloat162(h0, h1);
                    *reinterpret_cast<__nv_bfloat162*>(Clo + off) = __halves2bfloat162(l0, l1);
                } else {
                    *reinterpret_cast<float2*>(Cf + (size_t)row * Ntotal + col) =
                        make_float2(v0, v1);
                }
            }
        }
    }
}

// ---------------- driver -----------------------------------------------------
extern "C" void kernel_launch(void* const* d_in, const int* in_sizes, int n_in,
                              void* d_out, int out_size) {
    const float* x  = (const float*)d_in[0];
    const int*   ei = (const int*)d_in[1];       // int32 (JAX x64 disabled)
    const float* W1 = (const float*)d_in[2];
    const float* b1 = (const float*)d_in[3];
    const float* W2 = (const float*)d_in[4];
    const float* b2 = (const float*)d_in[5];
    const float* W3 = (const float*)d_in[6];
    const float* b3 = (const float*)d_in[7];
    float*       out = (float*)d_out;

    const int n = in_sizes[0] / F_IN;   // 50000
    const int e = in_sizes[1] / 2;      // 800000

    // Real device addresses of scratch globals.
    __nv_bfloat16 *s0h, *s0l, *s1h, *s1l, *w1h, *w1l, *w2h, *w2l, *w3h, *w3l;
    float *p_g2, *p_g3;
    cudaGetSymbolAddress((void**)&s0h, g_s0hi);
    cudaGetSymbolAddress((void**)&s0l, g_s0lo);
    cudaGetSymbolAddress((void**)&s1h, g_s1hi);
    cudaGetSymbolAddress((void**)&s1l, g_s1lo);
    cudaGetSymbolAddress((void**)&w1h, g_w1hi);
    cudaGetSymbolAddress((void**)&w1l, g_w1lo);
    cudaGetSymbolAddress((void**)&w2h, g_w2hi);
    cudaGetSymbolAddress((void**)&w2l, g_w2lo);
    cudaGetSymbolAddress((void**)&w3h, g_w3hi);
    cudaGetSymbolAddress((void**)&w3l, g_w3lo);
    cudaGetSymbolAddress((void**)&p_g2, g_g2);
    cudaGetSymbolAddress((void**)&p_g3, g_g3);

    // Dynamic smem: 2 stages x (2*128 + 2*NB) rows x 40 elems x 2B
    const int smem128 = 2 * (2 * 128 + 2 * 128) * 40 * 2;  // 81920
    const int smem32  = 2 * (2 * 128 + 2 * 32)  * 40 * 2;  // 51200
    cudaFuncSetAttribute(gemm_mma<128, 128, 4, 2, true,  true,  true,  false>,
                         cudaFuncAttributeMaxDynamicSharedMemorySize, smem128);
    cudaFuncSetAttribute(gemm_mma<128, 256, 4, 2, false, false, false, true >,
                         cudaFuncAttributeMaxDynamicSharedMemorySize, smem128);
    cudaFuncSetAttribute(gemm_mma<32,  128, 8, 1, false, false, false, true >,
                         cudaFuncAttributeMaxDynamicSharedMemorySize, smem32);

    const int mt = M_PAD / 128;         // 391 row tiles
    const int nb = (n + 1023) / 1024;   // scan blocks (49)

    // --- preprocessing (count zero from init / previous scan_add) ---
    degree_kernel<<<(e + 255) / 256, 256>>>(ei, e);
    scan_partial_dinv_kernel<<<nb, 1024>>>(n);
    scan_bsum_kernel<<<1, 64>>>(nb, n);
    scan_add_kernel<<<nb, 1024>>>(n);
    fill_csr_kernel<<<(e + 255) / 256, 256>>>(ei, e);

    // --- Layer 1: agg(x) -> split bf16; GEMM(128->256)+b1+relu -> split ---
    agg_kernel<F_IN, false, false, true, false><<<(n + 3) / 4, 128>>>(
        x, nullptr, nullptr, s0h, s0l, n);
    splitW_all<<<(256 * 128 + 128 * 256 + 32 * 128 + 255) / 256, 256>>>(
        W1, W2, W3, w1h, w1l, w2h, w2l, w3h, w3l);
    {
        dim3 grid(mt, 2);
        gemm_mma<128, 128, 4, 2, true, true, true, false><<<grid, 256, smem128>>>(
            s0h, s0l, w1h, w1l, b1, nullptr, s1h, s1l, n, F_H1);
    }

    // --- Layer 2: GEMM(256->128)*dinv -> fp32; agg(prescaled)+b2+relu -> split
    {
        dim3 grid(mt, 1);
        gemm_mma<128, 256, 4, 2, false, false, false, true><<<grid, 256, smem128>>>(
            s1h, s1l, w2h, w2l, nullptr, p_g2, nullptr, nullptr, n, F_H);
    }
    agg_kernel<F_H, true, true, true, true><<<(n + 3) / 4, 128>>>(
        p_g2, b2, nullptr, s0h, s0l, n);

    // --- Layer 3: GEMM(128->32)*dinv -> fp32; agg(prescaled)+b3 -> out ---
    {
        dim3 grid(mt, 1);
        gemm_mma<32, 128, 8, 1, false, false, false, true><<<grid, 256, smem32>>>(
            s0h, s0l, w3h, w3l, nullptr, p_g3, nullptr, nullptr, n, F_OUT);
    }
    agg_kernel<F_OUT, true, false, false, true><<<(n + 15) / 16, 128>>>(
        p_g3, b3, out, nullptr, nullptr, n);
}

// round 8
// speedup vs baseline: 3.3706x; 1.0378x over previous
#include <cuda_runtime.h>
#include <cuda_bf16.h>
#include <cuda_fp16.h>
#include <cstdint>

// Problem constants
#define N_NODES 50000
#define N_EDGES 800000
#define F_IN   128
#define F_H1   256
#define F_H    128
#define F_OUT  32
#define M_PAD  50048   // 391 * 128

// ---------------- scratch (static device globals) ---------------------------
__device__ int   g_count [N_NODES];
__device__ float g_dinv  [M_PAD];        // rows >= N_NODES stay 0
__device__ int   g_rowptr[N_NODES + 1];
__device__ int   g_cursor[N_NODES];
__device__ int   g_col   [N_EDGES];
__device__ int   g_bsum  [64];

// fp16 aggregation inputs (dinv-prescaled)
__device__ __half g_x16 [(size_t)N_NODES * F_IN];
__device__ __half g_g216[(size_t)M_PAD * F_H];
__device__ __half g_g316[(size_t)M_PAD * F_OUT];

// bf16 split activation buffers (GEMM inputs)
__device__ __nv_bfloat16 g_s0hi[(size_t)M_PAD * 256];
__device__ __nv_bfloat16 g_s0lo[(size_t)M_PAD * 256];
__device__ __nv_bfloat16 g_s1hi[(size_t)M_PAD * 256];
__device__ __nv_bfloat16 g_s1lo[(size_t)M_PAD * 256];
// transposed + split weights [N][K] (K-major rows)
__device__ __nv_bfloat16 g_w1hi[256 * 128], g_w1lo[256 * 128];
__device__ __nv_bfloat16 g_w2hi[128 * 256], g_w2lo[128 * 256];
__device__ __nv_bfloat16 g_w3hi[32 * 128],  g_w3lo[32 * 128];

// ---------------- PTX helpers ------------------------------------------------
__device__ __forceinline__ uint32_t smem_u32(const void* p) {
    uint32_t a;
    asm("{ .reg .u64 t; cvta.to.shared.u64 t, %1; cvt.u32.u64 %0, t; }"
        : "=r"(a) : "l"(p));
    return a;
}
__device__ __forceinline__ void ldsm4(uint32_t addr, uint32_t r[4]) {
    asm volatile("ldmatrix.sync.aligned.m8n8.x4.shared.b16 {%0,%1,%2,%3}, [%4];"
                 : "=r"(r[0]), "=r"(r[1]), "=r"(r[2]), "=r"(r[3]) : "r"(addr));
}
__device__ __forceinline__ void ldsm2(uint32_t addr, uint32_t r[2]) {
    asm volatile("ldmatrix.sync.aligned.m8n8.x2.shared.b16 {%0,%1}, [%2];"
                 : "=r"(r[0]), "=r"(r[1]) : "r"(addr));
}
__device__ __forceinline__ void mma16816(float* c, const uint32_t* a, const uint32_t* b) {
    asm volatile(
        "mma.sync.aligned.m16n8k16.row.col.f32.bf16.bf16.f32 "
        "{%0,%1,%2,%3}, {%4,%5,%6,%7}, {%8,%9}, {%0,%1,%2,%3};"
        : "+f"(c[0]), "+f"(c[1]), "+f"(c[2]), "+f"(c[3])
        : "r"(a[0]), "r"(a[1]), "r"(a[2]), "r"(a[3]), "r"(b[0]), "r"(b[1]));
}
__device__ __forceinline__ void cp16(uint32_t saddr, const void* gaddr) {
    asm volatile("cp.async.cg.shared.global [%0], [%1], 16;"
                 :: "r"(saddr), "l"(gaddr));
}
#define CP_COMMIT() asm volatile("cp.async.commit_group;" ::: "memory")

// ---------------- graph preprocessing ---------------------------------------
// edge_index int32: [2, E] row-major; src = ei[0:E], dst = ei[E:2E].
__global__ void degree_kernel(const int* __restrict__ ei, int e) {
    int i = blockIdx.x * blockDim.x + threadIdx.x;
    if (i < e) atomicAdd(&g_count[ei[e + i]], 1);
}

__global__ void scan_partial_dinv_kernel(int n) {
    __shared__ int temp[1024];
    int i = blockIdx.x * 1024 + threadIdx.x;
    int v = (i < n) ? g_count[i] : 0;
    if (i < n) g_dinv[i] = rsqrtf((float)(v + 1));  // fused dinv (+1 self-loop)
    temp[threadIdx.x] = v;
    __syncthreads();
    #pragma unroll
    for (int off = 1; off < 1024; off <<= 1) {
        int t = (threadIdx.x >= off) ? temp[threadIdx.x - off] : 0;
        __syncthreads();
        temp[threadIdx.x] += t;
        __syncthreads();
    }
    if (i < n) g_rowptr[i] = temp[threadIdx.x] - v;  // local exclusive
    if (threadIdx.x == 1023) g_bsum[blockIdx.x] = temp[1023];
}

__global__ void scan_bsum_kernel(int nb, int n) {
    __shared__ int t[64];
    int v = (threadIdx.x < nb) ? g_bsum[threadIdx.x] : 0;
    t[threadIdx.x] = v;
    __syncthreads();
    #pragma unroll
    for (int off = 1; off < 64; off <<= 1) {
        int u = (threadIdx.x >= off) ? t[threadIdx.x - off] : 0;
        __syncthreads();
        t[threadIdx.x] += u;
        __syncthreads();
    }
    if (threadIdx.x < nb) g_bsum[threadIdx.x] = t[threadIdx.x] - v;
    if (threadIdx.x == 63) g_rowptr[n] = t[63];
}

__global__ void scan_add_kernel(int n) {
    int i = blockIdx.x * 1024 + threadIdx.x;
    if (i < n) {
        int v = g_rowptr[i] + g_bsum[blockIdx.x];
        g_rowptr[i] = v;
        g_cursor[i] = v;
        g_count[i]  = 0;   // reset for next replay
    }
}

__global__ void fill_csr_kernel(const int* __restrict__ ei, int e) {
    int i = blockIdx.x * blockDim.x + threadIdx.x;
    if (i < e) {
        int src = ei[i];
        int dst = ei[e + i];
        int pos = atomicAdd(&g_cursor[dst], 1);
        g_col[pos] = src;
    }
}

// x -> dinv-prescaled fp16 (one thread per 8 features)
__global__ void conv_x16_kernel(const float* __restrict__ x,
                                __half* __restrict__ x16, int n) {
    int i = blockIdx.x * blockDim.x + threadIdx.x;
    int node = i >> 4, lane = i & 15;            // 16 threads/node (128 feats)
    if (node >= n) return;
    float di = g_dinv[node];
    const float4* xv = (const float4*)x;
    float4 a = xv[(size_t)node * 32 + lane * 2];
    float4 b = xv[(size_t)node * 32 + lane * 2 + 1];
    __half2 h0 = __floats2half2_rn(di * a.x, di * a.y);
    __half2 h1 = __floats2half2_rn(di * a.z, di * a.w);
    __half2 h2 = __floats2half2_rn(di * b.x, di * b.y);
    __half2 h3 = __floats2half2_rn(di * b.z, di * b.w);
    uint4 o;
    o.x = *reinterpret_cast<uint32_t*>(&h0);
    o.y = *reinterpret_cast<uint32_t*>(&h1);
    o.z = *reinterpret_cast<uint32_t*>(&h2);
    o.w = *reinterpret_cast<uint32_t*>(&h3);
    *reinterpret_cast<uint4*>(x16 + (size_t)node * F_IN + lane * 8) = o;
}

// ---------------- fp16 pull aggregation (uint4 = 8 halfs per load) -----------
// Input g is dinv[src]-prescaled fp16. out[d] = dinv[d]*(sum g[s] + g[d]) (+b)(relu)
__device__ __forceinline__ void add8h(float* acc, uint4 v) {
    const __half2* h = reinterpret_cast<const __half2*>(&v);
    #pragma unroll
    for (int q = 0; q < 4; q++) {
        float2 f = __half22float2(h[q]);
        acc[2 * q] += f.x; acc[2 * q + 1] += f.y;
    }
}

template <int F, bool BIAS, bool RELU, bool SPLIT>
__global__ void agg16_kernel(const __half* __restrict__ g,
                             const float* __restrict__ bias,
                             float* __restrict__ outf,
                             __nv_bfloat16* __restrict__ oh,
                             __nv_bfloat16* __restrict__ ol, int n) {
    constexpr int TPN = F / 8;
    int npb  = blockDim.x / TPN;
    int node = blockIdx.x * npb + threadIdx.x / TPN;
    if (node >= n) return;
    int lane = threadIdx.x % TPN;

    const uint4* gv = (const uint4*)g;           // row = TPN uint4s
    float acc[8];
    #pragma unroll
    for (int q = 0; q < 8; q++) acc[q] = 0.0f;
    add8h(acc, gv[(size_t)node * TPN + lane]);   // self loop (prescaled)

    int e  = g_rowptr[node];
    int e1 = g_rowptr[node + 1];
    for (; e + 8 <= e1; e += 8) {
        int  c[8];
        uint4 v[8];
        #pragma unroll
        for (int j = 0; j < 8; j++) c[j] = g_col[e + j];
        #pragma unroll
        for (int j = 0; j < 8; j++) v[j] = gv[(size_t)c[j] * TPN + lane];
        #pragma unroll
        for (int j = 0; j < 8; j++) add8h(acc, v[j]);
    }
    for (; e < e1; e++) add8h(acc, gv[(size_t)g_col[e] * TPN + lane]);

    float di = g_dinv[node];
    #pragma unroll
    for (int q = 0; q < 8; q++) acc[q] *= di;
    if (BIAS) {
        const float4* bp = (const float4*)(bias + lane * 8);
        float4 b0 = bp[0], b1 = bp[1];
        acc[0] += b0.x; acc[1] += b0.y; acc[2] += b0.z; acc[3] += b0.w;
        acc[4] += b1.x; acc[5] += b1.y; acc[6] += b1.z; acc[7] += b1.w;
    }
    if (RELU) {
        #pragma unroll
        for (int q = 0; q < 8; q++) acc[q] = fmaxf(acc[q], 0.0f);
    }
    if constexpr (SPLIT) {
        uint32_t hp[4], lp[4];
        #pragma unroll
        for (int q = 0; q < 4; q++) {
            __nv_bfloat16 h0 = __float2bfloat16(acc[2 * q]);
            __nv_bfloat16 h1 = __float2bfloat16(acc[2 * q + 1]);
            __nv_bfloat16 l0 = __float2bfloat16(acc[2 * q]     - __bfloat162float(h0));
            __nv_bfloat16 l1 = __float2bfloat16(acc[2 * q + 1] - __bfloat162float(h1));
            __nv_bfloat162 hh = __halves2bfloat162(h0, h1);
            __nv_bfloat162 ll = __halves2bfloat162(l0, l1);
            hp[q] = *reinterpret_cast<uint32_t*>(&hh);
            lp[q] = *reinterpret_cast<uint32_t*>(&ll);
        }
        size_t o = (size_t)node * F + lane * 8;
        *reinterpret_cast<uint4*>(oh + o) = make_uint4(hp[0], hp[1], hp[2], hp[3]);
        *reinterpret_cast<uint4*>(ol + o) = make_uint4(lp[0], lp[1], lp[2], lp[3]);
    } else {
        size_t o = (size_t)node * F + lane * 8;
        *reinterpret_cast<float4*>(outf + o)     = make_float4(acc[0], acc[1], acc[2], acc[3]);
        *reinterpret_cast<float4*>(outf + o + 4) = make_float4(acc[4], acc[5], acc[6], acc[7]);
    }
}

// ---------------- weight transpose + bf16 split (all 3 layers, 1 launch) ----
__global__ void splitW_all(const float* __restrict__ W1, const float* __restrict__ W2,
                           const float* __restrict__ W3,
                           __nv_bfloat16* w1h, __nv_bfloat16* w1l,
                           __nv_bfloat16* w2h, __nv_bfloat16* w2l,
                           __nv_bfloat16* w3h, __nv_bfloat16* w3l) {
    int idx = blockIdx.x * blockDim.x + threadIdx.x;
    float v; __nv_bfloat16* ph; __nv_bfloat16* pl; int o;
    if (idx < 256 * 128) {                       // W1 [128,256] -> [256][128]
        int nn = idx / 128, k = idx % 128;
        v = W1[k * 256 + nn]; ph = w1h; pl = w1l; o = idx;
    } else if (idx < 256 * 128 + 128 * 256) {    // W2 [256,128] -> [128][256]
        int i2 = idx - 256 * 128;
        int nn = i2 / 256, k = i2 % 256;
        v = W2[k * 128 + nn]; ph = w2h; pl = w2l; o = i2;
    } else if (idx < 256 * 128 + 128 * 256 + 32 * 128) {  // W3 [128,32] -> [32][128]
        int i3 = idx - 256 * 128 - 128 * 256;
        int nn = i3 / 128, k = i3 % 128;
        v = W3[k * 32 + nn]; ph = w3h; pl = w3l; o = i3;
    } else return;
    __nv_bfloat16 h = __float2bfloat16(v);
    ph[o] = h;
    pl[o] = __float2bfloat16(v - __bfloat162float(h));
}

// ---------------- mma.sync bf16-split GEMM, cp.async double-buffered --------
// C[M, Ntotal] = A[M, K] @ B^T, B stored [Ntotal][K].
// D += AhBh + AhBl + AlBh. Output: bf16-split OR dinv-scaled fp16.
template <int NB, int K, int WARPS_M, int WARPS_N, bool BIAS, bool RELU,
          bool SPLIT_OUT, bool DINV>
__global__ __launch_bounds__(32 * WARPS_M * WARPS_N)
void gemm_mma(const __nv_bfloat16* __restrict__ Ahi, const __nv_bfloat16* __restrict__ Alo,
              const __nv_bfloat16* __restrict__ Bhi, const __nv_bfloat16* __restrict__ Blo,
              const float* __restrict__ bias,
              __half* __restrict__ Ch, __nv_bfloat16* __restrict__ Chi,
              __nv_bfloat16* __restrict__ Clo, int M, int Ntotal) {
    constexpr int BM  = 128;
    constexpr int KC  = 32;
    constexpr int LDS = KC + 8;
    constexpr int NT  = 32 * WARPS_M * WARPS_N;
    constexpr int WM  = BM / WARPS_M;
    constexpr int WN  = NB / WARPS_N;
    constexpr int MF  = WM / 16;
    constexpr int NF  = WN / 8;
    constexpr int NCH = K / KC;
    constexpr int C8  = KC / 8;
    constexpr int AOFF_H = 0;
    constexpr int AOFF_L = BM * LDS;
    constexpr int BOFF_H = 2 * BM * LDS;
    constexpr int BOFF_L = 2 * BM * LDS + NB * LDS;
    constexpr int SSZ    = (2 * BM + 2 * NB) * LDS;

    extern __shared__ __nv_bfloat16 sm[];
    uint32_t u0 = smem_u32(sm);

    int tid  = threadIdx.x;
    int wid  = tid >> 5, lane = tid & 31;
    int wm0  = (wid / WARPS_N) * WM;
    int wn0  = (wid % WARPS_N) * WN;
    int m0   = blockIdx.x * BM;
    int n0   = blockIdx.y * NB;

    int a_r = lane & 15, a_c = (lane >> 4) * 8;
    int b_r = lane & 7,  b_c = ((lane >> 3) & 1) * 8;

    float acc[MF][NF][4];
    #pragma unroll
    for (int i = 0; i < MF; i++)
        #pragma unroll
        for (int j = 0; j < NF; j++)
            #pragma unroll
            for (int q = 0; q < 4; q++) acc[i][j][q] = 0.0f;

    auto issue = [&](int ch, int st) {
        int kc = ch * KC;
        uint32_t ub = u0 + (uint32_t)st * SSZ * 2;
        for (int i = tid; i < BM * C8; i += NT) {
            int r = i / C8, c = i % C8;
            uint32_t so = (uint32_t)(r * LDS + c * 8) * 2;
            size_t go = (size_t)(m0 + r) * K + kc + c * 8;
            cp16(ub + AOFF_H * 2 + so, Ahi + go);
            cp16(ub + AOFF_L * 2 + so, Alo + go);
        }
        for (int i = tid; i < NB * C8; i += NT) {
            int r = i / C8, c = i % C8;
            uint32_t so = (uint32_t)(r * LDS + c * 8) * 2;
            size_t go = (size_t)(n0 + r) * K + kc + c * 8;
            cp16(ub + BOFF_H * 2 + so, Bhi + go);
            cp16(ub + BOFF_L * 2 + so, Blo + go);
        }
        CP_COMMIT();
    };

    issue(0, 0);
    #pragma unroll
    for (int ch = 0; ch < NCH; ch++) {
        if (ch + 1 < NCH) {
            issue(ch + 1, (ch + 1) & 1);
            asm volatile("cp.async.wait_group 1;" ::: "memory");
        } else {
            asm volatile("cp.async.wait_group 0;" ::: "memory");
        }
        __syncthreads();

        uint32_t ub = u0 + (uint32_t)(ch & 1) * SSZ * 2;
        #pragma unroll
        for (int ks = 0; ks < KC / 16; ks++) {
            int k0 = ks * 16;
            uint32_t ah[MF][4], al[MF][4], bh[NF][2], bl[NF][2];
            #pragma unroll
            for (int i = 0; i < MF; i++) {
                uint32_t off = (uint32_t)((wm0 + i * 16 + a_r) * LDS + k0 + a_c) * 2;
                ldsm4(ub + AOFF_H * 2 + off, ah[i]);
                ldsm4(ub + AOFF_L * 2 + off, al[i]);
            }
            #pragma unroll
            for (int j = 0; j < NF; j++) {
                uint32_t off = (uint32_t)((wn0 + j * 8 + b_r) * LDS + k0 + b_c) * 2;
                ldsm2(ub + BOFF_H * 2 + off, bh[j]);
                ldsm2(ub + BOFF_L * 2 + off, bl[j]);
            }
            #pragma unroll
            for (int i = 0; i < MF; i++)
                #pragma unroll
                for (int j = 0; j < NF; j++) {
                    mma16816(acc[i][j], ah[i], bh[j]);
                    mma16816(acc[i][j], ah[i], bl[j]);
                    mma16816(acc[i][j], al[i], bh[j]);
                }
        }
        __syncthreads();
    }

    // ---- epilogue ----
    int gr = lane >> 2, t = lane & 3;
    #pragma unroll
    for (int i = 0; i < MF; i++) {
        #pragma unroll
        for (int j = 0; j < NF; j++) {
            int col = n0 + wn0 + j * 8 + 2 * t;
            #pragma unroll
            for (int h = 0; h < 2; h++) {
                int row = m0 + wm0 + i * 16 + gr + h * 8;
                float v0 = acc[i][j][h * 2 + 0];
                float v1 = acc[i][j][h * 2 + 1];
                if (BIAS) { v0 += bias[col]; v1 += bias[col + 1]; }
                if (RELU) { v0 = fmaxf(v0, 0.f); v1 = fmaxf(v1, 0.f); }
                if (DINV) { float d = g_dinv[row]; v0 *= d; v1 *= d; }
                if constexpr (SPLIT_OUT) {
                    __nv_bfloat16 h0 = __float2bfloat16(v0);
                    __nv_bfloat16 h1 = __float2bfloat16(v1);
                    __nv_bfloat16 l0 = __float2bfloat16(v0 - __bfloat162float(h0));
                    __nv_bfloat16 l1 = __float2bfloat16(v1 - __bfloat162float(h1));
                    size_t off = (size_t)row * Ntotal + col;
                    *reinterpret_cast<__nv_bfloat162*>(Chi + off) = __halves2bfloat162(h0, h1);
                    *reinterpret_cast<__nv_bfloat162*>(Clo + off) = __halves2bfloat162(l0, l1);
                } else {
                    *reinterpret_cast<__half2*>(Ch + (size_t)row * Ntotal + col) =
                        __floats2half2_rn(v0, v1);
                }
            }
        }
    }
}

// ---------------- driver -----------------------------------------------------
extern "C" void kernel_launch(void* const* d_in, const int* in_sizes, int n_in,
                              void* d_out, int out_size) {
    const float* x  = (const float*)d_in[0];
    const int*   ei = (const int*)d_in[1];       // int32 (JAX x64 disabled)
    const float* W1 = (const float*)d_in[2];
    const float* b1 = (const float*)d_in[3];
    const float* W2 = (const float*)d_in[4];
    const float* b2 = (const float*)d_in[5];
    const float* W3 = (const float*)d_in[6];
    const float* b3 = (const float*)d_in[7];
    float*       out = (float*)d_out;

    const int n = in_sizes[0] / F_IN;   // 50000
    const int e = in_sizes[1] / 2;      // 800000

    // Real device addresses of scratch globals.
    __nv_bfloat16 *s0h, *s0l, *s1h, *s1l, *w1h, *w1l, *w2h, *w2l, *w3h, *w3l;
    __half *x16, *g216, *g316;
    cudaGetSymbolAddress((void**)&s0h, g_s0hi);
    cudaGetSymbolAddress((void**)&s0l, g_s0lo);
    cudaGetSymbolAddress((void**)&s1h, g_s1hi);
    cudaGetSymbolAddress((void**)&s1l, g_s1lo);
    cudaGetSymbolAddress((void**)&w1h, g_w1hi);
    cudaGetSymbolAddress((void**)&w1l, g_w1lo);
    cudaGetSymbolAddress((void**)&w2h, g_w2hi);
    cudaGetSymbolAddress((void**)&w2l, g_w2lo);
    cudaGetSymbolAddress((void**)&w3h, g_w3hi);
    cudaGetSymbolAddress((void**)&w3l, g_w3lo);
    cudaGetSymbolAddress((void**)&x16,  g_x16);
    cudaGetSymbolAddress((void**)&g216, g_g216);
    cudaGetSymbolAddress((void**)&g316, g_g316);

    const int smem128 = 2 * (2 * 128 + 2 * 128) * 40 * 2;  // 81920
    const int smem32  = 2 * (2 * 128 + 2 * 32)  * 40 * 2;  // 51200
    cudaFuncSetAttribute(gemm_mma<128, 128, 4, 2, true,  true,  true,  false>,
                         cudaFuncAttributeMaxDynamicSharedMemorySize, smem128);
    cudaFuncSetAttribute(gemm_mma<128, 256, 4, 2, false, false, false, true >,
                         cudaFuncAttributeMaxDynamicSharedMemorySize, smem128);
    cudaFuncSetAttribute(gemm_mma<32,  128, 8, 1, false, false, false, true >,
                         cudaFuncAttributeMaxDynamicSharedMemorySize, smem32);

    const int mt = M_PAD / 128;         // 391 row tiles
    const int nb = (n + 1023) / 1024;   // scan blocks (49)

    // --- preprocessing: degree -> scan(+dinv) -> CSR ---
    degree_kernel<<<(e + 255) / 256, 256>>>(ei, e);
    scan_partial_dinv_kernel<<<nb, 1024>>>(n);
    scan_bsum_kernel<<<1, 64>>>(nb, n);
    scan_add_kernel<<<nb, 1024>>>(n);
    fill_csr_kernel<<<(e + 255) / 256, 256>>>(ei, e);
    conv_x16_kernel<<<(n * 16 + 255) / 256, 256>>>(x, x16, n);
    splitW_all<<<(256 * 128 + 128 * 256 + 32 * 128 + 255) / 256, 256>>>(
        W1, W2, W3, w1h, w1l, w2h, w2l, w3h, w3l);

    // --- Layer 1: agg16(x16) -> split bf16; GEMM(128->256)+b1+relu -> split --
    agg16_kernel<F_IN, false, false, true><<<(n + 7) / 8, 128>>>(
        x16, nullptr, nullptr, s0h, s0l, n);
    {
        dim3 grid(mt, 2);
        gemm_mma<128, 128, 4, 2, true, true, true, false><<<grid, 256, smem128>>>(
            s0h, s0l, w1h, w1l, b1, nullptr, s1h, s1l, n, F_H1);
    }

    // --- Layer 2: GEMM(256->128)*dinv -> fp16; agg16+b2+relu -> split ---
    {
        dim3 grid(mt, 1);
        gemm_mma<128, 256, 4, 2, false, false, false, true><<<grid, 256, smem128>>>(
            s1h, s1l, w2h, w2l, nullptr, g216, nullptr, nullptr, n, F_H);
    }
    agg16_kernel<F_H, true, true, true><<<(n + 7) / 8, 128>>>(
        g216, b2, nullptr, s0h, s0l, n);

    // --- Layer 3: GEMM(128->32)*dinv -> fp16; agg16+b3 -> out fp32 ---
    {
        dim3 grid(mt, 1);
        gemm_mma<32, 128, 8, 1, false, false, false, true><<<grid, 256, smem32>>>(
            s0h, s0l, w3h, w3l, nullptr, g316, nullptr, nullptr, n, F_OUT);
    }
    agg16_kernel<F_OUT, true, false, false><<<(n + 31) / 32, 128>>>(
        g316, b3, out, nullptr, nullptr, n);
}

// round 9
// speedup vs baseline: 3.7899x; 1.1244x over previous
#include <cuda_runtime.h>
#include <cuda_fp16.h>
#include <cstdint>

// Problem constants (fixed by dataset)
#define N_NODES 50000
#define N_EDGES 800000
#define F_IN   128
#define F_H1   256
#define F_H    128
#define F_OUT  32
#define M_PAD  50048   // 391 * 128

// ---------------- scratch (static device globals) ---------------------------
__device__ int   g_count [N_NODES];
__device__ float g_dinv  [M_PAD];        // pad rows stay 0
__device__ int   g_rowptr[N_NODES + 1];
__device__ int   g_cursor[N_NODES];
__device__ int   g_col   [N_EDGES];
__device__ int   g_pfx   [64];           // chained-scan prefix+flag (val+1; 0 = not ready)

// fp16 activations (pad rows of a1 stay zero -> downstream pad rows deterministic)
__device__ __half g_x16[(size_t)N_NODES * F_IN];   // plain fp16 x
__device__ __half g_a1 [(size_t)M_PAD * F_IN];     // agg1 out (GEMM1 A)
__device__ __half g_h1 [(size_t)M_PAD * F_H1];     // relu(a1@W1+b1)
__device__ __half g_g2 [(size_t)M_PAD * F_H];      // dinv*(h1@W2)
__device__ __half g_h2 [(size_t)M_PAD * F_H];      // relu(agg(g2)+b2)
__device__ __half g_g3 [(size_t)M_PAD * F_OUT];    // dinv*(h2@W3)
// transposed + fp16-split weights [N][K] (K-major rows)
__device__ __half g_w1h[256 * 128], g_w1l[256 * 128];
__device__ __half g_w2h[128 * 256], g_w2l[128 * 256];
__device__ __half g_w3h[32 * 128],  g_w3l[32 * 128];

// ---------------- PTX helpers ------------------------------------------------
__device__ __forceinline__ uint32_t smem_u32(const void* p) {
    uint32_t a;
    asm("{ .reg .u64 t; cvta.to.shared.u64 t, %1; cvt.u32.u64 %0, t; }"
        : "=r"(a) : "l"(p));
    return a;
}
__device__ __forceinline__ void ldsm4(uint32_t addr, uint32_t r[4]) {
    asm volatile("ldmatrix.sync.aligned.m8n8.x4.shared.b16 {%0,%1,%2,%3}, [%4];"
                 : "=r"(r[0]), "=r"(r[1]), "=r"(r[2]), "=r"(r[3]) : "r"(addr));
}
__device__ __forceinline__ void ldsm2(uint32_t addr, uint32_t r[2]) {
    asm volatile("ldmatrix.sync.aligned.m8n8.x2.shared.b16 {%0,%1}, [%2];"
                 : "=r"(r[0]), "=r"(r[1]) : "r"(addr));
}
__device__ __forceinline__ void mma16816h(float* c, const uint32_t* a, const uint32_t* b) {
    asm volatile(
        "mma.sync.aligned.m16n8k16.row.col.f32.f16.f16.f32 "
        "{%0,%1,%2,%3}, {%4,%5,%6,%7}, {%8,%9}, {%0,%1,%2,%3};"
        : "+f"(c[0]), "+f"(c[1]), "+f"(c[2]), "+f"(c[3])
        : "r"(a[0]), "r"(a[1]), "r"(a[2]), "r"(a[3]), "r"(b[0]), "r"(b[1]));
}
__device__ __forceinline__ void cp16(uint32_t saddr, const void* gaddr) {
    asm volatile("cp.async.cg.shared.global [%0], [%1], 16;"
                 :: "r"(saddr), "l"(gaddr));
}
#define CP_COMMIT() asm volatile("cp.async.commit_group;" ::: "memory")

// ---------------- launch 1: fused prep (degree + x->fp16 + splitW + flags) --
// sections by blockIdx.x; all independent.
__global__ __launch_bounds__(256)
void prep_kernel(const float* __restrict__ x, const int* __restrict__ ei,
                 const float* __restrict__ W1, const float* __restrict__ W2,
                 const float* __restrict__ W3,
                 __half* __restrict__ x16,
                 __half* w1h, __half* w1l, __half* w2h, __half* w2l,
                 __half* w3h, __half* w3l,
                 int n, int e, int B_deg, int B_conv, int B_w) {
    int bid = blockIdx.x, tid = threadIdx.x;
    if (bid < B_deg) {                                   // degree atomics
        int i = bid * 256 + tid;
        if (i < e) atomicAdd(&g_count[ei[e + i]], 1);
    } else if (bid < B_deg + B_conv) {                   // x -> plain fp16 (8/thr)
        int i = (bid - B_deg) * 256 + tid;               // n*16 threads
        int node = i >> 4, lane = i & 15;
        if (node >= n) return;
        const float4* xv = (const float4*)x;
        float4 a = xv[(size_t)node * 32 + lane * 2];
        float4 b = xv[(size_t)node * 32 + lane * 2 + 1];
        __half2 h0 = __floats2half2_rn(a.x, a.y);
        __half2 h1 = __floats2half2_rn(a.z, a.w);
        __half2 h2 = __floats2half2_rn(b.x, b.y);
        __half2 h3 = __floats2half2_rn(b.z, b.w);
        uint4 o;
        o.x = *reinterpret_cast<uint32_t*>(&h0);
        o.y = *reinterpret_cast<uint32_t*>(&h1);
        o.z = *reinterpret_cast<uint32_t*>(&h2);
        o.w = *reinterpret_cast<uint32_t*>(&h3);
        *reinterpret_cast<uint4*>(x16 + (size_t)node * F_IN + lane * 8) = o;
    } else if (bid < B_deg + B_conv + B_w) {             // weight transpose+split
        int idx = (bid - B_deg - B_conv) * 256 + tid;
        float v; __half* ph; __half* pl; int o;
        if (idx < 256 * 128) {                           // W1 [128,256] -> [256][128]
            int nn = idx / 128, k = idx % 128;
            v = W1[k * 256 + nn]; ph = w1h; pl = w1l; o = idx;
        } else if (idx < 2 * 32768) {                    // W2 [256,128] -> [128][256]
            int i2 = idx - 32768;
            int nn = i2 / 256, k = i2 % 256;
            v = W2[k * 128 + nn]; ph = w2h; pl = w2l; o = i2;
        } else if (idx < 2 * 32768 + 4096) {             // W3 [128,32] -> [32][128]
            int i3 = idx - 2 * 32768;
            int nn = i3 / 128, k = i3 % 128;
            v = W3[k * 32 + nn]; ph = w3h; pl = w3l; o = i3;
        } else return;
        __half h = __float2half(v);
        ph[o] = h;
        pl[o] = __float2half(v - __half2float(h));
    } else {                                             // zero scan flags
        if (tid < 64) g_pfx[tid] = 0;
    }
}

// ---------------- launch 2: chained single-pass scan -------------------------
// 49 blocks x 1024. dinv, rowptr (exclusive), cursor, count-reset.
__global__ __launch_bounds__(1024)
void scan_chained_kernel(int n, int nb) {
    __shared__ int temp[1024];
    __shared__ int pfx_sh;
    int bid = blockIdx.x, tid = threadIdx.x;
    int i = bid * 1024 + tid;
    int v = (i < n) ? g_count[i] : 0;
    if (i < n) {
        g_dinv[i]  = rsqrtf((float)(v + 1));   // +1 self-loop
        g_count[i] = 0;                        // reset for next replay
    }
    temp[tid] = v;
    __syncthreads();
    #pragma unroll
    for (int off = 1; off < 1024; off <<= 1) {
        int t = (tid >= off) ? temp[tid - off] : 0;
        __syncthreads();
        temp[tid] += t;
        __syncthreads();
    }
    if (tid == 0) {
        int p = 0;
        if (bid > 0) {
            while ((p = atomicAdd(&g_pfx[bid - 1], 0)) == 0) __nanosleep(20);
            p -= 1;                            // stored value+1
        }
        atomicExch(&g_pfx[bid], p + temp[1023] + 1);
        pfx_sh = p;
    }
    __syncthreads();
    int base = pfx_sh;
    if (i < n) {
        int excl = base + temp[tid] - v;
        g_rowptr[i] = excl;
        g_cursor[i] = excl;
    }
    if (bid == nb - 1 && tid == 1023) g_rowptr[n] = base + temp[1023];
}

// ---------------- launch 3: CSR fill ----------------------------------------
__global__ __launch_bounds__(256)
void fill_csr_kernel(const int* __restrict__ ei, int e) {
    int i = blockIdx.x * blockDim.x + threadIdx.x;
    if (i < e) {
        int src = ei[i];
        int dst = ei[e + i];
        int pos = atomicAdd(&g_cursor[dst], 1);
        g_col[pos] = src;
    }
}

// ---------------- fp16 pull aggregation --------------------------------------
__device__ __forceinline__ void add8s(float* acc, uint4 v, float d) {
    const __half2* h = reinterpret_cast<const __half2*>(&v);
    #pragma unroll
    for (int q = 0; q < 4; q++) {
        float2 f = __half22float2(h[q]);
        acc[2 * q]     = fmaf(d, f.x, acc[2 * q]);
        acc[2 * q + 1] = fmaf(d, f.y, acc[2 * q + 1]);
    }
}

// EDGE_DINV: g plain -> out = di*(di*g[d] + sum dinv[s]*g[s])
// else (prescaled): out = di*(g[d] + sum g[s])
// (+bias)(relu); OUT32 ? fp32 : fp16
template <int F, bool BIAS, bool RELU, bool EDGE_DINV, bool OUT32>
__global__ void agg16_kernel(const __half* __restrict__ g,
                             const float* __restrict__ bias,
                             __half* __restrict__ outh,
                             float* __restrict__ outf, int n) {
    constexpr int TPN = F / 8;
    int npb  = blockDim.x / TPN;
    int node = blockIdx.x * npb + threadIdx.x / TPN;
    if (node >= n) return;
    int lane = threadIdx.x % TPN;

    const uint4* gv = (const uint4*)g;
    float di = g_dinv[node];
    float acc[8];
    #pragma unroll
    for (int q = 0; q < 8; q++) acc[q] = 0.0f;
    add8s(acc, gv[(size_t)node * TPN + lane], EDGE_DINV ? di : 1.0f);  // self

    int e  = g_rowptr[node];
    int e1 = g_rowptr[node + 1];
    for (; e + 8 <= e1; e += 8) {
        int  c[8];
        uint4 v[8];
        #pragma unroll
        for (int j = 0; j < 8; j++) c[j] = g_col[e + j];
        #pragma unroll
        for (int j = 0; j < 8; j++) v[j] = gv[(size_t)c[j] * TPN + lane];
        if (EDGE_DINV) {
            float d[8];
            #pragma unroll
            for (int j = 0; j < 8; j++) d[j] = g_dinv[c[j]];
            #pragma unroll
            for (int j = 0; j < 8; j++) add8s(acc, v[j], d[j]);
        } else {
            #pragma unroll
            for (int j = 0; j < 8; j++) add8s(acc, v[j], 1.0f);
        }
    }
    for (; e < e1; e++) {
        int sv = g_col[e];
        add8s(acc, gv[(size_t)sv * TPN + lane], EDGE_DINV ? g_dinv[sv] : 1.0f);
    }

    #pragma unroll
    for (int q = 0; q < 8; q++) acc[q] *= di;
    if (BIAS) {
        const float4* bp = (const float4*)(bias + lane * 8);
        float4 b0 = bp[0], b1 = bp[1];
        acc[0] += b0.x; acc[1] += b0.y; acc[2] += b0.z; acc[3] += b0.w;
        acc[4] += b1.x; acc[5] += b1.y; acc[6] += b1.z; acc[7] += b1.w;
    }
    if (RELU) {
        #pragma unroll
        for (int q = 0; q < 8; q++) acc[q] = fmaxf(acc[q], 0.0f);
    }
    if constexpr (OUT32) {
        size_t o = (size_t)node * F + lane * 8;
        *reinterpret_cast<float4*>(outf + o)     = make_float4(acc[0], acc[1], acc[2], acc[3]);
        *reinterpret_cast<float4*>(outf + o + 4) = make_float4(acc[4], acc[5], acc[6], acc[7]);
    } else {
        uint4 o16;
        __half2 p0 = __floats2half2_rn(acc[0], acc[1]);
        __half2 p1 = __floats2half2_rn(acc[2], acc[3]);
        __half2 p2 = __floats2half2_rn(acc[4], acc[5]);
        __half2 p3 = __floats2half2_rn(acc[6], acc[7]);
        o16.x = *reinterpret_cast<uint32_t*>(&p0);
        o16.y = *reinterpret_cast<uint32_t*>(&p1);
        o16.z = *reinterpret_cast<uint32_t*>(&p2);
        o16.w = *reinterpret_cast<uint32_t*>(&p3);
        *reinterpret_cast<uint4*>(outh + (size_t)node * F + lane * 8) = o16;
    }
}

// ---------------- fp16 GEMM: A single x W split, cp.async 2-stage -----------
// C[M, Ntotal] = A[M,K] @ (Wh+Wl)^T, W stored [Ntotal][K].
// D += A*Wh + A*Wl (fp32 accum). Out fp16 (+bias)(relu)(*dinv[row]).
template <int NB, int K, int WARPS_M, int WARPS_N, bool BIAS, bool RELU, bool DINV>
__global__ __launch_bounds__(32 * WARPS_M * WARPS_N)
void gemm_f16(const __half* __restrict__ A,
              const __half* __restrict__ Wh, const __half* __restrict__ Wl,
              const float* __restrict__ bias,
              __half* __restrict__ C, int M, int Ntotal) {
    constexpr int BM  = 128;
    constexpr int KC  = 32;
    constexpr int LDS = KC + 8;
    constexpr int NT  = 32 * WARPS_M * WARPS_N;
    constexpr int WM  = BM / WARPS_M;
    constexpr int WN  = NB / WARPS_N;
    constexpr int MF  = WM / 16;
    constexpr int NF  = WN / 8;
    constexpr int NCH = K / KC;
    constexpr int C8  = KC / 8;
    constexpr int AOFF   = 0;
    constexpr int WOFF_H = BM * LDS;
    constexpr int WOFF_L = BM * LDS + NB * LDS;
    constexpr int SSZ    = (BM + 2 * NB) * LDS;

    extern __shared__ __half sm[];
    uint32_t u0 = smem_u32(sm);

    int tid  = threadIdx.x;
    int wid  = tid >> 5, lane = tid & 31;
    int wm0  = (wid / WARPS_N) * WM;
    int wn0  = (wid % WARPS_N) * WN;
    int m0   = blockIdx.x * BM;
    int n0   = blockIdx.y * NB;

    int a_r = lane & 15, a_c = (lane >> 4) * 8;
    int b_r = lane & 7,  b_c = ((lane >> 3) & 1) * 8;

    float acc[MF][NF][4];
    #pragma unroll
    for (int i = 0; i < MF; i++)
        #pragma unroll
        for (int j = 0; j < NF; j++)
            #pragma unroll
            for (int q = 0; q < 4; q++) acc[i][j][q] = 0.0f;

    auto issue = [&](int ch, int st) {
        int kc = ch * KC;
        uint32_t ub = u0 + (uint32_t)st * SSZ * 2;
        for (int i = tid; i < BM * C8; i += NT) {
            int r = i / C8, c = i % C8;
            cp16(ub + AOFF * 2 + (uint32_t)(r * LDS + c * 8) * 2,
                 A + (size_t)(m0 + r) * K + kc + c * 8);
        }
        for (int i = tid; i < NB * C8; i += NT) {
            int r = i / C8, c = i % C8;
            uint32_t so = (uint32_t)(r * LDS + c * 8) * 2;
            size_t go = (size_t)(n0 + r) * K + kc + c * 8;
            cp16(ub + WOFF_H * 2 + so, Wh + go);
            cp16(ub + WOFF_L * 2 + so, Wl + go);
        }
        CP_COMMIT();
    };

    issue(0, 0);
    #pragma unroll
    for (int ch = 0; ch < NCH; ch++) {
        if (ch + 1 < NCH) {
            issue(ch + 1, (ch + 1) & 1);
            asm volatile("cp.async.wait_group 1;" ::: "memory");
        } else {
            asm volatile("cp.async.wait_group 0;" ::: "memory");
        }
        __syncthreads();

        uint32_t ub = u0 + (uint32_t)(ch & 1) * SSZ * 2;
        #pragma unroll
        for (int ks = 0; ks < KC / 16; ks++) {
            int k0 = ks * 16;
            uint32_t a[MF][4], bh[NF][2], bl[NF][2];
            #pragma unroll
            for (int i = 0; i < MF; i++) {
                uint32_t off = (uint32_t)((wm0 + i * 16 + a_r) * LDS + k0 + a_c) * 2;
                ldsm4(ub + AOFF * 2 + off, a[i]);
            }
            #pragma unroll
            for (int j = 0; j < NF; j++) {
                uint32_t off = (uint32_t)((wn0 + j * 8 + b_r) * LDS + k0 + b_c) * 2;
                ldsm2(ub + WOFF_H * 2 + off, bh[j]);
                ldsm2(ub + WOFF_L * 2 + off, bl[j]);
            }
            #pragma unroll
            for (int i = 0; i < MF; i++)
                #pragma unroll
                for (int j = 0; j < NF; j++) {
                    mma16816h(acc[i][j], a[i], bh[j]);
                    mma16816h(acc[i][j], a[i], bl[j]);
                }
        }
        __syncthreads();
    }

    // ---- epilogue: fp16 out with fused bias/relu/dinv ----
    int gr = lane >> 2, t = lane & 3;
    #pragma unroll
    for (int i = 0; i < MF; i++) {
        #pragma unroll
        for (int j = 0; j < NF; j++) {
            int col = n0 + wn0 + j * 8 + 2 * t;
            #pragma unroll
            for (int h = 0; h < 2; h++) {
                int row = m0 + wm0 + i * 16 + gr + h * 8;
                float v0 = acc[i][j][h * 2 + 0];
                float v1 = acc[i][j][h * 2 + 1];
                if (BIAS) { v0 += bias[col]; v1 += bias[col + 1]; }
                if (RELU) { v0 = fmaxf(v0, 0.f); v1 = fmaxf(v1, 0.f); }
                if (DINV) { float d = g_dinv[row]; v0 *= d; v1 *= d; }
                *reinterpret_cast<__half2*>(C + (size_t)row * Ntotal + col) =
                    __floats2half2_rn(v0, v1);
            }
        }
    }
}

// ---------------- driver -----------------------------------------------------
extern "C" void kernel_launch(void* const* d_in, const int* in_sizes, int n_in,
                              void* d_out, int out_size) {
    const float* x  = (const float*)d_in[0];
    const int*   ei = (const int*)d_in[1];       // int32 (JAX x64 disabled)
    const float* W1 = (const float*)d_in[2];
    const float* b1 = (const float*)d_in[3];
    const float* W2 = (const float*)d_in[4];
    const float* b2 = (const float*)d_in[5];
    const float* W3 = (const float*)d_in[6];
    const float* b3 = (const float*)d_in[7];
    float*       out = (float*)d_out;

    const int n = in_sizes[0] / F_IN;   // 50000
    const int e = in_sizes[1] / 2;      // 800000

    __half *x16, *a1, *h1, *g2, *h2, *g3;
    __half *w1h, *w1l, *w2h, *w2l, *w3h, *w3l;
    cudaGetSymbolAddress((void**)&x16, g_x16);
    cudaGetSymbolAddress((void**)&a1,  g_a1);
    cudaGetSymbolAddress((void**)&h1,  g_h1);
    cudaGetSymbolAddress((void**)&g2,  g_g2);
    cudaGetSymbolAddress((void**)&h2,  g_h2);
    cudaGetSymbolAddress((void**)&g3,  g_g3);
    cudaGetSymbolAddress((void**)&w1h, g_w1h);
    cudaGetSymbolAddress((void**)&w1l, g_w1l);
    cudaGetSymbolAddress((void**)&w2h, g_w2h);
    cudaGetSymbolAddress((void**)&w2l, g_w2l);
    cudaGetSymbolAddress((void**)&w3h, g_w3h);
    cudaGetSymbolAddress((void**)&w3l, g_w3l);

    const int smem128 = 2 * (128 + 2 * 128) * 40 * 2;  // 61440
    const int smem32  = 2 * (128 + 2 * 32)  * 40 * 2;  // 30720
    cudaFuncSetAttribute(gemm_f16<128, 128, 4, 2, true,  true,  false>,
                         cudaFuncAttributeMaxDynamicSharedMemorySize, smem128);
    cudaFuncSetAttribute(gemm_f16<128, 256, 4, 2, false, false, true >,
                         cudaFuncAttributeMaxDynamicSharedMemorySize, smem128);
    cudaFuncSetAttribute(gemm_f16<32,  128, 8, 1, false, false, true >,
                         cudaFuncAttributeMaxDynamicSharedMemorySize, smem32);

    const int mt = M_PAD / 128;           // 391 row tiles
    const int nb = (n + 1023) / 1024;     // 49 scan blocks

    // launch 1: degree + x->fp16 + weight split + scan-flag reset
    const int B_deg  = (e + 255) / 256;               // 3125
    const int B_conv = (n * 16 + 255) / 256;          // 3125
    const int B_w    = (2 * 32768 + 4096 + 255) / 256; // 272
    prep_kernel<<<B_deg + B_conv + B_w + 1, 256>>>(
        x, ei, W1, W2, W3, x16, w1h, w1l, w2h, w2l, w3h, w3l,
        n, e, B_deg, B_conv, B_w);

    // launch 2: single-pass chained scan (dinv, rowptr, cursor, count reset)
    scan_chained_kernel<<<nb, 1024>>>(n, nb);

    // launch 3: CSR fill
    fill_csr_kernel<<<(e + 255) / 256, 256>>>(ei, e);

    // launch 4: agg1 (per-edge dinv) -> a1 fp16
    agg16_kernel<F_IN, false, false, true, false><<<(n + 7) / 8, 128>>>(
        x16, nullptr, a1, nullptr, n);

    // launch 5: GEMM1 (128->256) + b1 + relu -> h1 fp16
    {
        dim3 grid(mt, 2);
        gemm_f16<128, 128, 4, 2, true, true, false><<<grid, 256, smem128>>>(
            a1, w1h, w1l, b1, h1, n, F_H1);
    }

    // launch 6: GEMM2 (256->128) * dinv -> g2 fp16
    {
        dim3 grid(mt, 1);
        gemm_f16<128, 256, 4, 2, false, false, true><<<grid, 256, smem128>>>(
            h1, w2h, w2l, nullptr, g2, n, F_H);
    }

    // launch 7: agg2 (prescaled) + b2 + relu -> h2 fp16
    agg16_kernel<F_H, true, true, false, false><<<(n + 7) / 8, 128>>>(
        g2, b2, h2, nullptr, n);

    // launch 8: GEMM3 (128->32) * dinv -> g3 fp16
    {
        dim3 grid(mt, 1);
        gemm_f16<32, 128, 8, 1, false, false, true><<<grid, 256, smem32>>>(
            h2, w3h, w3l, nullptr, g3, n, F_OUT);
    }

    // launch 9: agg3 (prescaled) + b3 -> out fp32
    agg16_kernel<F_OUT, true, false, false, true><<<(n + 31) / 32, 128>>>(
        g3, b3, nullptr, out, n);
}

// round 10
// speedup vs baseline: 4.2906x; 1.1321x over previous
#include <cuda_runtime.h>
#include <cuda_fp16.h>
#include <cstdint>

// Problem constants (fixed by dataset)
#define N_NODES 50000
#define N_EDGES 800000
#define F_IN   128
#define F_H1   256
#define F_H    128
#define F_OUT  32
#define M_PAD  50048   // 391 * 128

// ---------------- scratch (static device globals) ---------------------------
__device__ int   g_count [N_NODES];
__device__ float g_dinv  [M_PAD];        // pad rows stay 0
__device__ int   g_rowptr[N_NODES + 1];
__device__ int   g_cursor[N_NODES];
__device__ int   g_col   [N_EDGES];
__device__ int   g_pfx   [64];           // chained-scan prefix (+1; 0 = not ready)

// fp16 activations
__device__ __half g_x16[(size_t)N_NODES * F_IN];   // x -> fp16, then dinv-prescaled
__device__ __half g_a1 [(size_t)M_PAD * F_IN];     // agg1 out (GEMM1 A)
__device__ __half g_h1 [(size_t)M_PAD * F_H1];     // relu(a1@W1+b1)
__device__ __half g_g2 [(size_t)M_PAD * F_H];      // dinv*(h1@W2)
__device__ __half g_h2 [(size_t)M_PAD * F_H];      // relu(agg(g2)+b2)
__device__ __half g_g3 [(size_t)M_PAD * F_OUT];    // dinv*(h2@W3)
// transposed fp16 weights [N][K] (K-major rows)
__device__ __half g_w1[256 * 128];
__device__ __half g_w2[128 * 256];
__device__ __half g_w3[32 * 128];

// ---------------- PTX helpers ------------------------------------------------
__device__ __forceinline__ uint32_t smem_u32(const void* p) {
    uint32_t a;
    asm("{ .reg .u64 t; cvta.to.shared.u64 t, %1; cvt.u32.u64 %0, t; }"
        : "=r"(a) : "l"(p));
    return a;
}
__device__ __forceinline__ void ldsm4(uint32_t addr, uint32_t r[4]) {
    asm volatile("ldmatrix.sync.aligned.m8n8.x4.shared.b16 {%0,%1,%2,%3}, [%4];"
                 : "=r"(r[0]), "=r"(r[1]), "=r"(r[2]), "=r"(r[3]) : "r"(addr));
}
__device__ __forceinline__ void ldsm2(uint32_t addr, uint32_t r[2]) {
    asm volatile("ldmatrix.sync.aligned.m8n8.x2.shared.b16 {%0,%1}, [%2];"
                 : "=r"(r[0]), "=r"(r[1]) : "r"(addr));
}
__device__ __forceinline__ void mma16816h(float* c, const uint32_t* a, const uint32_t* b) {
    asm volatile(
        "mma.sync.aligned.m16n8k16.row.col.f32.f16.f16.f32 "
        "{%0,%1,%2,%3}, {%4,%5,%6,%7}, {%8,%9}, {%0,%1,%2,%3};"
        : "+f"(c[0]), "+f"(c[1]), "+f"(c[2]), "+f"(c[3])
        : "r"(a[0]), "r"(a[1]), "r"(a[2]), "r"(a[3]), "r"(b[0]), "r"(b[1]));
}
__device__ __forceinline__ void cp16(uint32_t saddr, const void* gaddr) {
    asm volatile("cp.async.cg.shared.global [%0], [%1], 16;"
                 :: "r"(saddr), "l"(gaddr));
}
#define CP_COMMIT() asm volatile("cp.async.commit_group;" ::: "memory")

// ---------------- launch 1: fused prep (degree + x->fp16 + W transp + flags) -
__global__ __launch_bounds__(256)
void prep_kernel(const float* __restrict__ x, const int* __restrict__ ei,
                 const float* __restrict__ W1, const float* __restrict__ W2,
                 const float* __restrict__ W3,
                 __half* __restrict__ x16,
                 __half* w1, __half* w2, __half* w3,
                 int n, int e, int B_deg, int B_conv, int B_w) {
    int bid = blockIdx.x, tid = threadIdx.x;
    if (bid < B_deg) {                                   // degree atomics
        int i = bid * 256 + tid;
        if (i < e) atomicAdd(&g_count[ei[e + i]], 1);
    } else if (bid < B_deg + B_conv) {                   // x -> fp16 (8/thr)
        int i = (bid - B_deg) * 256 + tid;
        int node = i >> 4, lane = i & 15;
        if (node >= n) return;
        const float4* xv = (const float4*)x;
        float4 a = xv[(size_t)node * 32 + lane * 2];
        float4 b = xv[(size_t)node * 32 + lane * 2 + 1];
        __half2 h0 = __floats2half2_rn(a.x, a.y);
        __half2 h1 = __floats2half2_rn(a.z, a.w);
        __half2 h2 = __floats2half2_rn(b.x, b.y);
        __half2 h3 = __floats2half2_rn(b.z, b.w);
        uint4 o;
        o.x = *reinterpret_cast<uint32_t*>(&h0);
        o.y = *reinterpret_cast<uint32_t*>(&h1);
        o.z = *reinterpret_cast<uint32_t*>(&h2);
        o.w = *reinterpret_cast<uint32_t*>(&h3);
        *reinterpret_cast<uint4*>(x16 + (size_t)node * F_IN + lane * 8) = o;
    } else if (bid < B_deg + B_conv + B_w) {             // weight transpose (fp16)
        int idx = (bid - B_deg - B_conv) * 256 + tid;
        if (idx < 32768) {                               // W1 [128,256] -> [256][128]
            int nn = idx / 128, k = idx % 128;
            w1[idx] = __float2half(W1[k * 256 + nn]);
        } else if (idx < 65536) {                        // W2 [256,128] -> [128][256]
            int i2 = idx - 32768;
            int nn = i2 / 256, k = i2 % 256;
            w2[i2] = __float2half(W2[k * 128 + nn]);
        } else if (idx < 65536 + 4096) {                 // W3 [128,32] -> [32][128]
            int i3 = idx - 65536;
            int nn = i3 / 128, k = i3 % 128;
            w3[i3] = __float2half(W3[k * 32 + nn]);
        }
    } else {                                             // zero scan flags
        if (tid < 64) g_pfx[tid] = 0;
    }
}

// ---------------- launch 2: chained single-pass scan -------------------------
__global__ __launch_bounds__(1024)
void scan_chained_kernel(int n, int nb) {
    __shared__ int temp[1024];
    __shared__ int pfx_sh;
    int bid = blockIdx.x, tid = threadIdx.x;
    int i = bid * 1024 + tid;
    int v = (i < n) ? g_count[i] : 0;
    if (i < n) {
        g_dinv[i]  = rsqrtf((float)(v + 1));   // +1 self-loop
        g_count[i] = 0;                        // reset for next replay
    }
    temp[tid] = v;
    __syncthreads();
    #pragma unroll
    for (int off = 1; off < 1024; off <<= 1) {
        int t = (tid >= off) ? temp[tid - off] : 0;
        __syncthreads();
        temp[tid] += t;
        __syncthreads();
    }
    if (tid == 0) {
        int p = 0;
        if (bid > 0) {
            while ((p = atomicAdd(&g_pfx[bid - 1], 0)) == 0) __nanosleep(20);
            p -= 1;
        }
        atomicExch(&g_pfx[bid], p + temp[1023] + 1);
        pfx_sh = p;
    }
    __syncthreads();
    int base = pfx_sh;
    if (i < n) {
        int excl = base + temp[tid] - v;
        g_rowptr[i] = excl;
        g_cursor[i] = excl;
    }
    if (bid == nb - 1 && tid == 1023) g_rowptr[n] = base + temp[1023];
}

// ---------------- launch 3: CSR fill ----------------------------------------
__global__ __launch_bounds__(256)
void fill_csr_kernel(const int* __restrict__ ei, int e) {
    int i = blockIdx.x * blockDim.x + threadIdx.x;
    if (i < e) {
        int src = ei[i];
        int dst = ei[e + i];
        int pos = atomicAdd(&g_cursor[dst], 1);
        g_col[pos] = src;
    }
}

// ---------------- launch 4: x16 *= dinv (in place) ---------------------------
__global__ __launch_bounds__(256)
void prescale_kernel(__half* __restrict__ x16, int n) {
    int i = blockIdx.x * blockDim.x + threadIdx.x;
    int node = i >> 4, lane = i & 15;
    if (node >= n) return;
    float di = g_dinv[node];
    uint4 v = *reinterpret_cast<uint4*>(x16 + (size_t)node * F_IN + lane * 8);
    __half2* h = reinterpret_cast<__half2*>(&v);
    #pragma unroll
    for (int q = 0; q < 4; q++) {
        float2 f = __half22float2(h[q]);
        h[q] = __floats2half2_rn(di * f.x, di * f.y);
    }
    *reinterpret_cast<uint4*>(x16 + (size_t)node * F_IN + lane * 8) = v;
}

// ---------------- fp16 pull aggregation (prescaled, pairwise hadd2) ----------
__device__ __forceinline__ void add8(float* acc, uint4 v) {
    const __half2* h = reinterpret_cast<const __half2*>(&v);
    #pragma unroll
    for (int q = 0; q < 4; q++) {
        float2 f = __half22float2(h[q]);
        acc[2 * q] += f.x; acc[2 * q + 1] += f.y;
    }
}
__device__ __forceinline__ uint4 hadd2x4(uint4 a, uint4 b) {
    const __half2* pa = reinterpret_cast<const __half2*>(&a);
    const __half2* pb = reinterpret_cast<const __half2*>(&b);
    uint4 r;
    __half2* pr = reinterpret_cast<__half2*>(&r);
    #pragma unroll
    for (int q = 0; q < 4; q++) pr[q] = __hadd2(pa[q], pb[q]);
    return r;
}

// out[d] = dinv[d]*(g[d] + sum g[s]) (+bias)(relu); g rows dinv[src]-prescaled.
template <int F, bool BIAS, bool RELU, bool OUT32>
__global__ void agg16_kernel(const __half* __restrict__ g,
                             const float* __restrict__ bias,
                             __half* __restrict__ outh,
                             float* __restrict__ outf, int n) {
    constexpr int TPN = F / 8;
    constexpr uint32_t RB = F * 2;     // row bytes (fits 32-bit total: <13MB)
    int npb  = blockDim.x / TPN;
    int node = blockIdx.x * npb + threadIdx.x / TPN;
    if (node >= n) return;
    int lane = threadIdx.x % TPN;

    const char* base = (const char*)g + lane * 16;
    float acc[8];
    #pragma unroll
    for (int q = 0; q < 8; q++) acc[q] = 0.0f;
    add8(acc, *reinterpret_cast<const uint4*>(base + (uint32_t)node * RB));  // self

    int e  = g_rowptr[node];
    int e1 = g_rowptr[node + 1];
    for (; e + 8 <= e1; e += 8) {
        uint32_t off[8];
        uint4 v[8];
        #pragma unroll
        for (int j = 0; j < 8; j++) off[j] = (uint32_t)g_col[e + j] * RB;
        #pragma unroll
        for (int j = 0; j < 8; j++) v[j] = *reinterpret_cast<const uint4*>(base + off[j]);
        #pragma unroll
        for (int p = 0; p < 4; p++) {             // one-level fp16 pairwise
            uint4 w = hadd2x4(v[2 * p], v[2 * p + 1]);
            add8(acc, w);
        }
    }
    for (; e < e1; e++)
        add8(acc, *reinterpret_cast<const uint4*>(base + (uint32_t)g_col[e] * RB));

    float di = g_dinv[node];
    #pragma unroll
    for (int q = 0; q < 8; q++) acc[q] *= di;
    if (BIAS) {
        const float4* bp = (const float4*)(bias + lane * 8);
        float4 b0 = bp[0], b1 = bp[1];
        acc[0] += b0.x; acc[1] += b0.y; acc[2] += b0.z; acc[3] += b0.w;
        acc[4] += b1.x; acc[5] += b1.y; acc[6] += b1.z; acc[7] += b1.w;
    }
    if (RELU) {
        #pragma unroll
        for (int q = 0; q < 8; q++) acc[q] = fmaxf(acc[q], 0.0f);
    }
    if constexpr (OUT32) {
        size_t o = (size_t)node * F + lane * 8;
        *reinterpret_cast<float4*>(outf + o)     = make_float4(acc[0], acc[1], acc[2], acc[3]);
        *reinterpret_cast<float4*>(outf + o + 4) = make_float4(acc[4], acc[5], acc[6], acc[7]);
    } else {
        uint4 o16;
        __half2 p0 = __floats2half2_rn(acc[0], acc[1]);
        __half2 p1 = __floats2half2_rn(acc[2], acc[3]);
        __half2 p2 = __floats2half2_rn(acc[4], acc[5]);
        __half2 p3 = __floats2half2_rn(acc[6], acc[7]);
        o16.x = *reinterpret_cast<uint32_t*>(&p0);
        o16.y = *reinterpret_cast<uint32_t*>(&p1);
        o16.z = *reinterpret_cast<uint32_t*>(&p2);
        o16.w = *reinterpret_cast<uint32_t*>(&p3);
        *reinterpret_cast<uint4*>(outh + (size_t)node * F + lane * 8) = o16;
    }
}

// ---------------- fp16 GEMM (single W), cp.async 2-stage ---------------------
// C[M, Ntotal] = A[M,K] @ W^T, W stored [Ntotal][K]. fp32 accum.
template <int NB, int K, int WARPS_M, int WARPS_N, bool BIAS, bool RELU, bool DINV>
__global__ __launch_bounds__(32 * WARPS_M * WARPS_N)
void gemm_f16(const __half* __restrict__ A, const __half* __restrict__ W,
              const float* __restrict__ bias,
              __half* __restrict__ C, int M, int Ntotal) {
    constexpr int BM  = 128;
    constexpr int KC  = 32;
    constexpr int LDS = KC + 8;
    constexpr int NT  = 32 * WARPS_M * WARPS_N;
    constexpr int WM  = BM / WARPS_M;
    constexpr int WN  = NB / WARPS_N;
    constexpr int MF  = WM / 16;
    constexpr int NF  = WN / 8;
    constexpr int NCH = K / KC;
    constexpr int C8  = KC / 8;
    constexpr int AOFF = 0;
    constexpr int WOFF = BM * LDS;
    constexpr int SSZ  = (BM + NB) * LDS;

    extern __shared__ __half sm[];
    uint32_t u0 = smem_u32(sm);

    int tid  = threadIdx.x;
    int wid  = tid >> 5, lane = tid & 31;
    int wm0  = (wid / WARPS_N) * WM;
    int wn0  = (wid % WARPS_N) * WN;
    int m0   = blockIdx.x * BM;
    int n0   = blockIdx.y * NB;

    int a_r = lane & 15, a_c = (lane >> 4) * 8;
    int b_r = lane & 7,  b_c = ((lane >> 3) & 1) * 8;

    float acc[MF][NF][4];
    #pragma unroll
    for (int i = 0; i < MF; i++)
        #pragma unroll
        for (int j = 0; j < NF; j++)
            #pragma unroll
            for (int q = 0; q < 4; q++) acc[i][j][q] = 0.0f;

    auto issue = [&](int ch, int st) {
        int kc = ch * KC;
        uint32_t ub = u0 + (uint32_t)st * SSZ * 2;
        for (int i = tid; i < BM * C8; i += NT) {
            int r = i / C8, c = i % C8;
            cp16(ub + AOFF * 2 + (uint32_t)(r * LDS + c * 8) * 2,
                 A + (size_t)(m0 + r) * K + kc + c * 8);
        }
        for (int i = tid; i < NB * C8; i += NT) {
            int r = i / C8, c = i % C8;
            cp16(ub + WOFF * 2 + (uint32_t)(r * LDS + c * 8) * 2,
                 W + (size_t)(n0 + r) * K + kc + c * 8);
        }
        CP_COMMIT();
    };

    issue(0, 0);
    #pragma unroll
    for (int ch = 0; ch < NCH; ch++) {
        if (ch + 1 < NCH) {
            issue(ch + 1, (ch + 1) & 1);
            asm volatile("cp.async.wait_group 1;" ::: "memory");
        } else {
            asm volatile("cp.async.wait_group 0;" ::: "memory");
        }
        __syncthreads();

        uint32_t ub = u0 + (uint32_t)(ch & 1) * SSZ * 2;
        #pragma unroll
        for (int ks = 0; ks < KC / 16; ks++) {
            int k0 = ks * 16;
            uint32_t a[MF][4], b[NF][2];
            #pragma unroll
            for (int i = 0; i < MF; i++) {
                uint32_t off = (uint32_t)((wm0 + i * 16 + a_r) * LDS + k0 + a_c) * 2;
                ldsm4(ub + AOFF * 2 + off, a[i]);
            }
            #pragma unroll
            for (int j = 0; j < NF; j++) {
                uint32_t off = (uint32_t)((wn0 + j * 8 + b_r) * LDS + k0 + b_c) * 2;
                ldsm2(ub + WOFF * 2 + off, b[j]);
            }
            #pragma unroll
            for (int i = 0; i < MF; i++)
                #pragma unroll
                for (int j = 0; j < NF; j++)
                    mma16816h(acc[i][j], a[i], b[j]);
        }
        __syncthreads();
    }

    // ---- epilogue: fp16 out with fused bias/relu/dinv ----
    int gr = lane >> 2, t = lane & 3;
    #pragma unroll
    for (int i = 0; i < MF; i++) {
        #pragma unroll
        for (int j = 0; j < NF; j++) {
            int col = n0 + wn0 + j * 8 + 2 * t;
            #pragma unroll
            for (int h = 0; h < 2; h++) {
                int row = m0 + wm0 + i * 16 + gr + h * 8;
                float v0 = acc[i][j][h * 2 + 0];
                float v1 = acc[i][j][h * 2 + 1];
                if (BIAS) { v0 += bias[col]; v1 += bias[col + 1]; }
                if (RELU) { v0 = fmaxf(v0, 0.f); v1 = fmaxf(v1, 0.f); }
                if (DINV) { float d = g_dinv[row]; v0 *= d; v1 *= d; }
                *reinterpret_cast<__half2*>(C + (size_t)row * Ntotal + col) =
                    __floats2half2_rn(v0, v1);
            }
        }
    }
}

// ---------------- driver -----------------------------------------------------
extern "C" void kernel_launch(void* const* d_in, const int* in_sizes, int n_in,
                              void* d_out, int out_size) {
    const float* x  = (const float*)d_in[0];
    const int*   ei = (const int*)d_in[1];       // int32 (JAX x64 disabled)
    const float* W1 = (const float*)d_in[2];
    const float* b1 = (const float*)d_in[3];
    const float* W2 = (const float*)d_in[4];
    const float* b2 = (const float*)d_in[5];
    const float* W3 = (const float*)d_in[6];
    const float* b3 = (const float*)d_in[7];
    float*       out = (float*)d_out;

    const int n = in_sizes[0] / F_IN;   // 50000
    const int e = in_sizes[1] / 2;      // 800000

    __half *x16, *a1, *h1, *g2, *h2, *g3, *w1, *w2, *w3;
    cudaGetSymbolAddress((void**)&x16, g_x16);
    cudaGetSymbolAddress((void**)&a1,  g_a1);
    cudaGetSymbolAddress((void**)&h1,  g_h1);
    cudaGetSymbolAddress((void**)&g2,  g_g2);
    cudaGetSymbolAddress((void**)&h2,  g_h2);
    cudaGetSymbolAddress((void**)&g3,  g_g3);
    cudaGetSymbolAddress((void**)&w1,  g_w1);
    cudaGetSymbolAddress((void**)&w2,  g_w2);
    cudaGetSymbolAddress((void**)&w3,  g_w3);

    const int smem128 = 2 * (128 + 128) * 40 * 2;  // 40960
    const int smem32  = 2 * (128 + 32)  * 40 * 2;  // 25600
    cudaFuncSetAttribute(gemm_f16<128, 128, 4, 2, true,  true,  false>,
                         cudaFuncAttributeMaxDynamicSharedMemorySize, smem128);
    cudaFuncSetAttribute(gemm_f16<128, 256, 4, 2, false, false, true >,
                         cudaFuncAttributeMaxDynamicSharedMemorySize, smem128);
    cudaFuncSetAttribute(gemm_f16<32,  128, 8, 1, false, false, true >,
                         cudaFuncAttributeMaxDynamicSharedMemorySize, smem32);

    const int mt = M_PAD / 128;           // 391 row tiles
    const int nb = (n + 1023) / 1024;     // 49 scan blocks

    // launch 1: degree + x->fp16 + weight transpose + scan-flag reset
    const int B_deg  = (e + 255) / 256;
    const int B_conv = (n * 16 + 255) / 256;
    const int B_w    = (65536 + 4096 + 255) / 256;
    prep_kernel<<<B_deg + B_conv + B_w + 1, 256>>>(
        x, ei, W1, W2, W3, x16, w1, w2, w3, n, e, B_deg, B_conv, B_w);

    // launch 2: chained scan (dinv, rowptr, cursor, count reset)
    scan_chained_kernel<<<nb, 1024>>>(n, nb);

    // launch 3: CSR fill
    fill_csr_kernel<<<(e + 255) / 256, 256>>>(ei, e);

    // launch 4: x16 *= dinv
    prescale_kernel<<<(n * 16 + 255) / 256, 256>>>(x16, n);

    // launch 5: agg1 (pure sum) -> a1
    agg16_kernel<F_IN, false, false, false><<<(n + 7) / 8, 128>>>(
        x16, nullptr, a1, nullptr, n);

    // launch 6: GEMM1 (128->256) + b1 + relu -> h1
    {
        dim3 grid(mt, 2);
        gemm_f16<128, 128, 4, 2, true, true, false><<<grid, 256, smem128>>>(
            a1, w1, b1, h1, n, F_H1);
    }

    // launch 7: GEMM2 (256->128) * dinv -> g2
    {
        dim3 grid(mt, 1);
        gemm_f16<128, 256, 4, 2, false, false, true><<<grid, 256, smem128>>>(
            h1, w2, nullptr, g2, n, F_H);
    }

    // launch 8: agg2 + b2 + relu -> h2
    agg16_kernel<F_H, true, true, false><<<(n + 7) / 8, 128>>>(
        g2, b2, h2, nullptr, n);

    // launch 9: GEMM3 (128->32) * dinv -> g3
    {
        dim3 grid(mt, 1);
        gemm_f16<32, 128, 8, 1, false, false, true><<<grid, 256, smem32>>>(
            h2, w3, nullptr, g3, n, F_OUT);
    }

    // launch 10: agg3 + b3 -> out fp32
    agg16_kernel<F_OUT, true, false, true><<<(n + 31) / 32, 128>>>(
        g3, b3, nullptr, out, n);
}